// round 11
// baseline (speedup 1.0000x reference)
#include <cuda_runtime.h>
#include <float.h>

#define BB 16
#define NN_ 4096
#define SS 1024

// ---------------- scratch (device globals: allowed) ----------------
__device__ __align__(16) float g_Wft [384 * 128];   // [k][o] fuse weights (NO BN fold)
__device__ __align__(16) float g_W1t [128 * 128];   // [k][o]
__device__ __align__(16) float g_W2t [128 * 128];   // [k][o]
__device__ __align__(16) float g_scale_f[128], g_bias_f[128];
__device__ __align__(16) float g_scale_1[128], g_bias_1[128];
__device__ __align__(16) float g_scale_2[128], g_bias_2[128];
__device__ __align__(16) float g_p2t[(size_t)BB * SS * 256];  // [b][s][c] 16 MB
__device__ __align__(16) int   g_idx4[(size_t)BB * NN_ * 4];
__device__ __align__(16) float g_w4 [(size_t)BB * NN_ * 4];

// ---------------- packed f32x2 helpers (sm_103a) ----------------
__device__ __forceinline__ unsigned long long pack2(float v)
{
    unsigned long long r;
    asm("mov.b64 %0, {%1, %1};" : "=l"(r) : "f"(v));
    return r;
}
__device__ __forceinline__ void ffma2(unsigned long long& acc,
                                      unsigned long long w,
                                      unsigned long long x)
{
    asm("fma.rn.f32x2 %0, %1, %2, %3;" : "=l"(acc) : "l"(w), "l"(x), "l"(acc));
}
__device__ __forceinline__ void unpack2(unsigned long long p, float& lo, float& hi)
{
    asm("mov.b64 {%0, %1}, %2;" : "=f"(lo), "=f"(hi) : "l"(p));
}

// ---------------- prep: transpose weights; BN -> epilogue ----------------
__global__ void prep_kernel(
    const float* __restrict__ fw, const float* __restrict__ fb,
    const float* __restrict__ fg, const float* __restrict__ fbeta,
    const float* __restrict__ fm, const float* __restrict__ fv,
    const float* __restrict__ w1, const float* __restrict__ b1,
    const float* __restrict__ g1, const float* __restrict__ be1,
    const float* __restrict__ m1, const float* __restrict__ v1,
    const float* __restrict__ w2, const float* __restrict__ b2,
    const float* __restrict__ g2, const float* __restrict__ be2,
    const float* __restrict__ m2, const float* __restrict__ v2)
{
    const int total = 384 + 384 * 128 + 128 * 128 + 128 * 128;
    for (int i = blockIdx.x * blockDim.x + threadIdx.x; i < total;
         i += gridDim.x * blockDim.x) {
        int t = i;
        if (t < 384) {
            int o = t & 127, which = t >> 7;
            if (which == 0) {
                float a = fg[o] * rsqrtf(fv[o] + 1e-5f);
                g_scale_f[o] = a;
                g_bias_f[o]  = a * (fb[o] - fm[o]) + fbeta[o];
            } else if (which == 1) {
                float a = g1[o] * rsqrtf(v1[o] + 1e-5f);
                g_scale_1[o] = a;
                g_bias_1[o]  = a * (b1[o] - m1[o]) + be1[o];
            } else {
                float a = g2[o] * rsqrtf(v2[o] + 1e-5f);
                g_scale_2[o] = a;
                g_bias_2[o]  = a * (b2[o] - m2[o]) + be2[o];
            }
            continue;
        }
        t -= 384;
        if (t < 384 * 128) {               // fuse: [o][384] -> [k][o]
            int k = t >> 7, o = t & 127;
            g_Wft[k * 128 + o] = fw[o * 384 + k];
            continue;
        }
        t -= 384 * 128;
        if (t < 128 * 128) {
            int k = t >> 7, o = t & 127;
            g_W1t[k * 128 + o] = w1[o * 128 + k];
            continue;
        }
        t -= 128 * 128;
        {
            int k = t >> 7, o = t & 127;
            g_W2t[k * 128 + o] = w2[o * 128 + k];
        }
    }
}

// ---------------- transpose p2: [b][c][s] -> [b][s][c] ----------------
__global__ void transpose_kernel(const float* __restrict__ p2)
{
    __shared__ float t[32][33];
    int b = blockIdx.z, c0 = blockIdx.y * 32, s0 = blockIdx.x * 32;
    int tx = threadIdx.x, ty = threadIdx.y;
#pragma unroll
    for (int i = 0; i < 32; i += 8)
        t[ty + i][tx] = p2[((size_t)b * 256 + c0 + ty + i) * SS + s0 + tx];
    __syncthreads();
#pragma unroll
    for (int i = 0; i < 32; i += 8)
        g_p2t[((size_t)b * SS + s0 + ty + i) * 256 + c0 + tx] = t[tx][ty + i];
}

// ---------------- 3-NN + weights: form F5 (JAX-GPU lowering) ----------
// DO NOT TOUCH: numerics verified (rel_err 9.32e-4, passing).
//   sq  = fma(z,z, fma(y,y, rn(x*x)))
//   dot = fma(a2,b2, fma(a1,b1, rn(a0*b0)))
//   d   = rn( rn(sq1 + sq2) - 2*dot )
__global__ __launch_bounds__(256) void knn_kernel(
    const float* __restrict__ xyz1, const float* __restrict__ xyz2)
{
    __shared__ __align__(16) float4 sc[SS];
    int b = blockIdx.y;
    int n = blockIdx.x * 256 + threadIdx.x;

    const float* x2 = xyz2 + (size_t)b * SS * 3;
    for (int s = threadIdx.x; s < SS; s += 256) {
        float cx = x2[s * 3 + 0], cy = x2[s * 3 + 1], cz = x2[s * 3 + 2];
        float sq2 = __fmaf_rn(cz, cz, __fmaf_rn(cy, cy, __fmul_rn(cx, cx)));
        sc[s] = make_float4(cx, cy, cz, sq2);
    }
    __syncthreads();

    const float* q = xyz1 + ((size_t)b * NN_ + n) * 3;
    float qx = q[0], qy = q[1], qz = q[2];
    float sq1 = __fmaf_rn(qz, qz, __fmaf_rn(qy, qy, __fmul_rn(qx, qx)));

    float d0 = FLT_MAX, d1 = FLT_MAX, d2 = FLT_MAX;
    int   i0 = 0, i1 = 0, i2 = 0;

#pragma unroll 4
    for (int s = 0; s < SS; s++) {
        float4 c = sc[s];
        float dot = __fmaf_rn(qz, c.z, __fmaf_rn(qy, c.y, __fmul_rn(qx, c.x)));
        float d = __fsub_rn(__fadd_rn(sq1, c.w), __fadd_rn(dot, dot));
        if (d < d2) {
            if (d < d1) {
                d2 = d1; i2 = i1;
                if (d < d0) { d1 = d0; i1 = i0; d0 = d; i0 = s; }
                else        { d1 = d;  i1 = s; }
            } else { d2 = d; i2 = s; }
        }
    }

    float r0 = __fdiv_rn(1.0f, __fadd_rn(d0, 1e-8f));
    float r1 = __fdiv_rn(1.0f, __fadd_rn(d1, 1e-8f));
    float r2 = __fdiv_rn(1.0f, __fadd_rn(d2, 1e-8f));
    float sum = __fadd_rn(__fadd_rn(r0, r1), r2);

    size_t gi = ((size_t)b * NN_ + n) * 4;
    g_idx4[gi + 0] = i0; g_idx4[gi + 1] = i1;
    g_idx4[gi + 2] = i2; g_idx4[gi + 3] = i2;
    g_w4 [gi + 0] = __fdiv_rn(r0, sum);
    g_w4 [gi + 1] = __fdiv_rn(r1, sum);
    g_w4 [gi + 2] = __fdiv_rn(r2, sum);
    g_w4 [gi + 3] = 0.0f;
}

// ---------------- packed GEMM tile (FFMA2, 4o x 4n per thread) ----------
// acc2[wp][ni] holds outputs (o+2*wp, o+2*wp+1) for point nn+ni.
// One ulonglong2 weight load (o..o+3, pre-packed pairs) + one float4 x load
// per k. Bit-exact vs scalar: same per-element fp32 FMA chain and order.
__device__ __forceinline__ void gemm_tileK2(const float* __restrict__ wb,
                                            const float* __restrict__ ib,
                                            int kcnt, int o, int nn,
                                            unsigned long long acc2[2][4])
{
#pragma unroll 4
    for (int k = 0; k < kcnt; k++) {
        ulonglong2 wA = *(const ulonglong2*)(wb + k * 128 + o);  // (o,o+1),(o+2,o+3)
        float4 xv = *(const float4*)(ib + k * 64 + nn);
        unsigned long long x0 = pack2(xv.x), x1 = pack2(xv.y);
        unsigned long long x2 = pack2(xv.z), x3 = pack2(xv.w);
        ffma2(acc2[0][0], wA.x, x0); ffma2(acc2[0][1], wA.x, x1);
        ffma2(acc2[0][2], wA.x, x2); ffma2(acc2[0][3], wA.x, x3);
        ffma2(acc2[1][0], wA.y, x0); ffma2(acc2[1][1], wA.y, x1);
        ffma2(acc2[1][2], wA.y, x2); ffma2(acc2[1][3], wA.y, x3);
    }
}

__device__ __forceinline__ void zero_acc(unsigned long long acc2[2][4])
{
#pragma unroll
    for (int wp = 0; wp < 2; wp++)
#pragma unroll
        for (int ni = 0; ni < 4; ni++) acc2[wp][ni] = 0ULL;
}

__device__ __forceinline__ void unpack_acc(const unsigned long long acc2[2][4],
                                           float acc[4][4])
{
#pragma unroll
    for (int wp = 0; wp < 2; wp++)
#pragma unroll
        for (int ni = 0; ni < 4; ni++)
            unpack2(acc2[wp][ni], acc[2 * wp][ni], acc[2 * wp + 1][ni]);
}

// ---------------- fused MLP: interp + fuse(K=384) + residual block ------
// 512 threads (16 warps, 4/SMSP) for latency hiding; per-thread tile 4o x 4n.
// smem: ibuf 384x64 (96KB) | wbuf 2x 64x128 halves (64KB)
__global__ __launch_bounds__(512) void mlp_kernel(
    const float* __restrict__ p1, float* __restrict__ out)
{
    extern __shared__ __align__(16) float smem[];
    float* ibuf = smem;             // 24576 floats
    float* wbuf = smem + 24576;     // 16384 floats

    int b   = blockIdx.y;
    int n0  = blockIdx.x * 64;
    int tid = threadIdx.x;
    int o   = (tid >> 4) * 4;       // 32 o-groups of 4
    int nn  = (tid & 15) * 4;       // 16 n-groups of 4

    // --- stage p1 tile into ibuf rows 0..127 ---
    for (int i = tid; i < 2048; i += 512) {
        int c = i >> 4, nq = i & 15;
        ((float4*)ibuf)[i] =
            *(const float4*)(p1 + ((size_t)b * 128 + c) * NN_ + n0 + nq * 4);
    }

    // --- interp (4-way gather; 4th weight is 0) -> rows 128..383 ---
    {
        int pt = tid >> 3, part = tid & 7;          // 64 pts x 8 threads (32 ch each)
        size_t gi = ((size_t)b * NN_ + n0 + pt) * 4;
        int4   jj = *(const int4*)(g_idx4 + gi);
        float4 ww = *(const float4*)(g_w4 + gi);
        const float4* ra = (const float4*)(g_p2t + ((size_t)b * SS + jj.x) * 256 + part * 32);
        const float4* rb = (const float4*)(g_p2t + ((size_t)b * SS + jj.y) * 256 + part * 32);
        const float4* rc = (const float4*)(g_p2t + ((size_t)b * SS + jj.z) * 256 + part * 32);
        const float4* rd = (const float4*)(g_p2t + ((size_t)b * SS + jj.w) * 256 + part * 32);
#pragma unroll
        for (int it = 0; it < 8; it++) {
            float4 a = ra[it], bb = rb[it], cc = rc[it], dd = rd[it];
            float v0 = fmaf(ww.w, dd.x, fmaf(ww.z, cc.x, fmaf(ww.y, bb.x, ww.x * a.x)));
            float v1 = fmaf(ww.w, dd.y, fmaf(ww.z, cc.y, fmaf(ww.y, bb.y, ww.x * a.y)));
            float v2 = fmaf(ww.w, dd.z, fmaf(ww.z, cc.z, fmaf(ww.y, bb.z, ww.x * a.z)));
            float v3 = fmaf(ww.w, dd.w, fmaf(ww.z, cc.w, fmaf(ww.y, bb.w, ww.x * a.w)));
            int cbase = 128 + part * 32 + it * 4;
            ibuf[(cbase + 0) * 64 + pt] = v0;
            ibuf[(cbase + 1) * 64 + pt] = v1;
            ibuf[(cbase + 2) * 64 + pt] = v2;
            ibuf[(cbase + 3) * 64 + pt] = v3;
        }
    }

    // --- fuse GEMM: K=384 in 6 chunks of 64, double-buffered weights ---
    unsigned long long acc2[2][4];
    zero_acc(acc2);

    const float4* wsrc = (const float4*)g_Wft;   // 384*128/4 = 12288 float4
    float4 pre[4];
#pragma unroll
    for (int i = 0; i < 4; i++) pre[i] = wsrc[tid + i * 512];

    for (int c = 0; c < 6; c++) {
        float* wb = wbuf + (c & 1) * 8192;
        __syncthreads();                         // prev users done w/ this half (c=0: covers ibuf staging)
#pragma unroll
        for (int i = 0; i < 4; i++) ((float4*)wb)[tid + i * 512] = pre[i];
        __syncthreads();
        if (c < 5) {
#pragma unroll
            for (int i = 0; i < 4; i++)
                pre[i] = wsrc[(c + 1) * 2048 + tid + i * 512];
        }
        gemm_tileK2(wb, ibuf + c * 64 * 64, 64, o, nn, acc2);
    }

    // --- fuse epilogue: BN + ReLU (fp32), keep fp32 residual ---
    float acc[4][4];
    unpack_acc(acc2, acc);
    float xres[4][4];
    {
        float4 s0 = *(const float4*)(g_scale_f + o);
        float4 t0 = *(const float4*)(g_bias_f + o);
        float sv[4] = {s0.x, s0.y, s0.z, s0.w};
        float tv[4] = {t0.x, t0.y, t0.z, t0.w};
#pragma unroll
        for (int oi = 0; oi < 4; oi++)
#pragma unroll
            for (int ni = 0; ni < 4; ni++)
                xres[oi][ni] = fmaxf(fmaf(sv[oi], acc[oi][ni], tv[oi]), 0.0f);
    }
    __syncthreads();    // all threads done reading ibuf (fuse) and wbuf
#pragma unroll
    for (int oi = 0; oi < 4; oi++)
        *(float4*)(ibuf + (o + oi) * 64 + nn) =
            make_float4(xres[oi][0], xres[oi][1], xres[oi][2], xres[oi][3]);
    for (int i = tid; i < 4096; i += 512)
        ((float4*)wbuf)[i] = ((const float4*)g_W1t)[i];
    __syncthreads();

    // --- c1: h = relu(bn1(W1 x)) ---
    zero_acc(acc2);
    gemm_tileK2(wbuf, ibuf, 128, o, nn, acc2);
    unpack_acc(acc2, acc);
    {
        float4 s0 = *(const float4*)(g_scale_1 + o);
        float4 t0 = *(const float4*)(g_bias_1 + o);
        float sv[4] = {s0.x, s0.y, s0.z, s0.w};
        float tv[4] = {t0.x, t0.y, t0.z, t0.w};
#pragma unroll
        for (int oi = 0; oi < 4; oi++)
#pragma unroll
            for (int ni = 0; ni < 4; ni++)
                acc[oi][ni] = fmaxf(fmaf(sv[oi], acc[oi][ni], tv[oi]), 0.0f);
    }
    __syncthreads();    // done reading ibuf(x) / wbuf(W1)
#pragma unroll
    for (int oi = 0; oi < 4; oi++)
        *(float4*)(ibuf + 8192 + (o + oi) * 64 + nn) =
            make_float4(acc[oi][0], acc[oi][1], acc[oi][2], acc[oi][3]);
    for (int i = tid; i < 4096; i += 512)
        ((float4*)wbuf)[i] = ((const float4*)g_W2t)[i];
    __syncthreads();

    // --- c2 + residual: out = relu(bn2(W2 h) + x) ---
    zero_acc(acc2);
    gemm_tileK2(wbuf, ibuf + 8192, 128, o, nn, acc2);
    unpack_acc(acc2, acc);
    {
        float4 s0 = *(const float4*)(g_scale_2 + o);
        float4 t0 = *(const float4*)(g_bias_2 + o);
        float sv[4] = {s0.x, s0.y, s0.z, s0.w};
        float tv[4] = {t0.x, t0.y, t0.z, t0.w};
#pragma unroll
        for (int oi = 0; oi < 4; oi++) {
            float* op = out + ((size_t)b * 128 + o + oi) * NN_ + n0 + nn;
            *(float4*)op = make_float4(
                fmaxf(fmaf(sv[oi], acc[oi][0], tv[oi]) + xres[oi][0], 0.0f),
                fmaxf(fmaf(sv[oi], acc[oi][1], tv[oi]) + xres[oi][1], 0.0f),
                fmaxf(fmaf(sv[oi], acc[oi][2], tv[oi]) + xres[oi][2], 0.0f),
                fmaxf(fmaf(sv[oi], acc[oi][3], tv[oi]) + xres[oi][3], 0.0f));
        }
    }
}

// ---------------- launch ----------------
extern "C" void kernel_launch(void* const* d_in, const int* in_sizes, int n_in,
                              void* d_out, int out_size)
{
    const float* xyz1      = (const float*)d_in[0];
    const float* xyz2      = (const float*)d_in[1];
    const float* points1   = (const float*)d_in[2];
    const float* points2   = (const float*)d_in[3];
    const float* fuse_w    = (const float*)d_in[4];
    const float* fuse_b    = (const float*)d_in[5];
    const float* fuse_g    = (const float*)d_in[6];
    const float* fuse_beta = (const float*)d_in[7];
    const float* fuse_m    = (const float*)d_in[8];
    const float* fuse_v    = (const float*)d_in[9];
    const float* c1_w      = (const float*)d_in[10];
    const float* c1_b      = (const float*)d_in[11];
    const float* bn1_g     = (const float*)d_in[12];
    const float* bn1_b     = (const float*)d_in[13];
    const float* bn1_m     = (const float*)d_in[14];
    const float* bn1_v     = (const float*)d_in[15];
    const float* c2_w      = (const float*)d_in[16];
    const float* c2_b      = (const float*)d_in[17];
    const float* bn2_g     = (const float*)d_in[18];
    const float* bn2_b     = (const float*)d_in[19];
    const float* bn2_m     = (const float*)d_in[20];
    const float* bn2_v     = (const float*)d_in[21];
    float* out = (float*)d_out;

    cudaFuncSetAttribute(mlp_kernel,
                         cudaFuncAttributeMaxDynamicSharedMemorySize, 163840);

    prep_kernel<<<128, 256>>>(fuse_w, fuse_b, fuse_g, fuse_beta, fuse_m, fuse_v,
                              c1_w, c1_b, bn1_g, bn1_b, bn1_m, bn1_v,
                              c2_w, c2_b, bn2_g, bn2_b, bn2_m, bn2_v);
    transpose_kernel<<<dim3(SS / 32, 256 / 32, BB), dim3(32, 8)>>>(points2);
    knn_kernel<<<dim3(NN_ / 256, BB), 256>>>(xyz1, xyz2);
    mlp_kernel<<<dim3(NN_ / 64, BB), 512, 163840>>>(points1, out);
}

// round 12
// speedup vs baseline: 1.2311x; 1.2311x over previous
#include <cuda_runtime.h>
#include <float.h>

#define BB 16
#define NN_ 4096
#define SS 1024
#define NT 128   // points per block tile

// ---------------- scratch (device globals: allowed) ----------------
__device__ __align__(16) float g_Wft [384 * 128];   // [k][o] fuse weights (NO BN fold)
__device__ __align__(16) float g_W1t [128 * 128];   // [k][o]
__device__ __align__(16) float g_W2t [128 * 128];   // [k][o]
__device__ __align__(16) float g_scale_f[128], g_bias_f[128];
__device__ __align__(16) float g_scale_1[128], g_bias_1[128];
__device__ __align__(16) float g_scale_2[128], g_bias_2[128];
__device__ __align__(16) float g_p2t[(size_t)BB * SS * 256];  // [b][s][c] 16 MB
__device__ __align__(16) int   g_idx4[(size_t)BB * NN_ * 4];
__device__ __align__(16) float g_w4 [(size_t)BB * NN_ * 4];

// ---------------- packed f32x2 helpers (sm_103a) ----------------
__device__ __forceinline__ unsigned long long pack2(float v)
{
    unsigned long long r;
    asm("mov.b64 %0, {%1, %1};" : "=l"(r) : "f"(v));
    return r;
}
__device__ __forceinline__ void ffma2(unsigned long long& acc,
                                      unsigned long long w,
                                      unsigned long long x)
{
    asm("fma.rn.f32x2 %0, %1, %2, %3;" : "=l"(acc) : "l"(w), "l"(x), "l"(acc));
}
__device__ __forceinline__ void unpack2(unsigned long long p, float& lo, float& hi)
{
    asm("mov.b64 {%0, %1}, %2;" : "=f"(lo), "=f"(hi) : "l"(p));
}

// ---------------- prep: transpose weights; BN -> epilogue ----------------
__global__ void prep_kernel(
    const float* __restrict__ fw, const float* __restrict__ fb,
    const float* __restrict__ fg, const float* __restrict__ fbeta,
    const float* __restrict__ fm, const float* __restrict__ fv,
    const float* __restrict__ w1, const float* __restrict__ b1,
    const float* __restrict__ g1, const float* __restrict__ be1,
    const float* __restrict__ m1, const float* __restrict__ v1,
    const float* __restrict__ w2, const float* __restrict__ b2,
    const float* __restrict__ g2, const float* __restrict__ be2,
    const float* __restrict__ m2, const float* __restrict__ v2)
{
    const int total = 384 + 384 * 128 + 128 * 128 + 128 * 128;
    for (int i = blockIdx.x * blockDim.x + threadIdx.x; i < total;
         i += gridDim.x * blockDim.x) {
        int t = i;
        if (t < 384) {
            int o = t & 127, which = t >> 7;
            if (which == 0) {
                float a = fg[o] * rsqrtf(fv[o] + 1e-5f);
                g_scale_f[o] = a;
                g_bias_f[o]  = a * (fb[o] - fm[o]) + fbeta[o];
            } else if (which == 1) {
                float a = g1[o] * rsqrtf(v1[o] + 1e-5f);
                g_scale_1[o] = a;
                g_bias_1[o]  = a * (b1[o] - m1[o]) + be1[o];
            } else {
                float a = g2[o] * rsqrtf(v2[o] + 1e-5f);
                g_scale_2[o] = a;
                g_bias_2[o]  = a * (b2[o] - m2[o]) + be2[o];
            }
            continue;
        }
        t -= 384;
        if (t < 384 * 128) {               // fuse: [o][384] -> [k][o]
            int k = t >> 7, o = t & 127;
            g_Wft[k * 128 + o] = fw[o * 384 + k];
            continue;
        }
        t -= 384 * 128;
        if (t < 128 * 128) {
            int k = t >> 7, o = t & 127;
            g_W1t[k * 128 + o] = w1[o * 128 + k];
            continue;
        }
        t -= 128 * 128;
        {
            int k = t >> 7, o = t & 127;
            g_W2t[k * 128 + o] = w2[o * 128 + k];
        }
    }
}

// ---------------- transpose p2: [b][c][s] -> [b][s][c] ----------------
__global__ void transpose_kernel(const float* __restrict__ p2)
{
    __shared__ float t[32][33];
    int b = blockIdx.z, c0 = blockIdx.y * 32, s0 = blockIdx.x * 32;
    int tx = threadIdx.x, ty = threadIdx.y;
#pragma unroll
    for (int i = 0; i < 32; i += 8)
        t[ty + i][tx] = p2[((size_t)b * 256 + c0 + ty + i) * SS + s0 + tx];
    __syncthreads();
#pragma unroll
    for (int i = 0; i < 32; i += 8)
        g_p2t[((size_t)b * SS + s0 + ty + i) * 256 + c0 + tx] = t[tx][ty + i];
}

// ---------------- 3-NN + weights: form F5 (JAX-GPU lowering) ----------
// DO NOT TOUCH: numerics verified (rel_err 9.32e-4, passing).
__global__ __launch_bounds__(256) void knn_kernel(
    const float* __restrict__ xyz1, const float* __restrict__ xyz2)
{
    __shared__ __align__(16) float4 sc[SS];
    int b = blockIdx.y;
    int n = blockIdx.x * 256 + threadIdx.x;

    const float* x2 = xyz2 + (size_t)b * SS * 3;
    for (int s = threadIdx.x; s < SS; s += 256) {
        float cx = x2[s * 3 + 0], cy = x2[s * 3 + 1], cz = x2[s * 3 + 2];
        float sq2 = __fmaf_rn(cz, cz, __fmaf_rn(cy, cy, __fmul_rn(cx, cx)));
        sc[s] = make_float4(cx, cy, cz, sq2);
    }
    __syncthreads();

    const float* q = xyz1 + ((size_t)b * NN_ + n) * 3;
    float qx = q[0], qy = q[1], qz = q[2];
    float sq1 = __fmaf_rn(qz, qz, __fmaf_rn(qy, qy, __fmul_rn(qx, qx)));

    float d0 = FLT_MAX, d1 = FLT_MAX, d2 = FLT_MAX;
    int   i0 = 0, i1 = 0, i2 = 0;

#pragma unroll 4
    for (int s = 0; s < SS; s++) {
        float4 c = sc[s];
        float dot = __fmaf_rn(qz, c.z, __fmaf_rn(qy, c.y, __fmul_rn(qx, c.x)));
        float d = __fsub_rn(__fadd_rn(sq1, c.w), __fadd_rn(dot, dot));
        if (d < d2) {
            if (d < d1) {
                d2 = d1; i2 = i1;
                if (d < d0) { d1 = d0; i1 = i0; d0 = d; i0 = s; }
                else        { d1 = d;  i1 = s; }
            } else { d2 = d; i2 = s; }
        }
    }

    float r0 = __fdiv_rn(1.0f, __fadd_rn(d0, 1e-8f));
    float r1 = __fdiv_rn(1.0f, __fadd_rn(d1, 1e-8f));
    float r2 = __fdiv_rn(1.0f, __fadd_rn(d2, 1e-8f));
    float sum = __fadd_rn(__fadd_rn(r0, r1), r2);

    size_t gi = ((size_t)b * NN_ + n) * 4;
    g_idx4[gi + 0] = i0; g_idx4[gi + 1] = i1;
    g_idx4[gi + 2] = i2; g_idx4[gi + 3] = i2;
    g_w4 [gi + 0] = __fdiv_rn(r0, sum);
    g_w4 [gi + 1] = __fdiv_rn(r1, sum);
    g_w4 [gi + 2] = __fdiv_rn(r2, sum);
    g_w4 [gi + 3] = 0.0f;
}

// ---------------- packed GEMM 64-k chunk (FFMA2, 8o x 4n per thread) -----
// Weight loads are warp-uniform (o = wid*8) -> full broadcast LDS.
// Bit-exact vs scalar: one fp32 FMA per output per k, k ascending.
__device__ __forceinline__ void gemm_chunk(const float* __restrict__ wb,
                                           const float* __restrict__ xb,
                                           int o, int nn,
                                           unsigned long long acc2[4][4])
{
#pragma unroll 4
    for (int k = 0; k < 64; k++) {
        ulonglong2 wA = *(const ulonglong2*)(wb + k * 128 + o);      // (o,o+1),(o+2,o+3)
        ulonglong2 wB = *(const ulonglong2*)(wb + k * 128 + o + 4);  // (o+4,o+5),(o+6,o+7)
        float4 xv = *(const float4*)(xb + k * NT + nn);
        unsigned long long x0 = pack2(xv.x), x1 = pack2(xv.y);
        unsigned long long x2 = pack2(xv.z), x3 = pack2(xv.w);
        ffma2(acc2[0][0], wA.x, x0); ffma2(acc2[0][1], wA.x, x1);
        ffma2(acc2[0][2], wA.x, x2); ffma2(acc2[0][3], wA.x, x3);
        ffma2(acc2[1][0], wA.y, x0); ffma2(acc2[1][1], wA.y, x1);
        ffma2(acc2[1][2], wA.y, x2); ffma2(acc2[1][3], wA.y, x3);
        ffma2(acc2[2][0], wB.x, x0); ffma2(acc2[2][1], wB.x, x1);
        ffma2(acc2[2][2], wB.x, x2); ffma2(acc2[2][3], wB.x, x3);
        ffma2(acc2[3][0], wB.y, x0); ffma2(acc2[3][1], wB.y, x1);
        ffma2(acc2[3][2], wB.y, x2); ffma2(acc2[3][3], wB.y, x3);
    }
}

__device__ __forceinline__ void zero_acc(unsigned long long acc2[4][4])
{
#pragma unroll
    for (int wp = 0; wp < 4; wp++)
#pragma unroll
        for (int ni = 0; ni < 4; ni++) acc2[wp][ni] = 0ULL;
}

__device__ __forceinline__ void unpack_acc(const unsigned long long acc2[4][4],
                                           float acc[8][4])
{
#pragma unroll
    for (int wp = 0; wp < 4; wp++)
#pragma unroll
        for (int ni = 0; ni < 4; ni++)
            unpack2(acc2[wp][ni], acc[2 * wp][ni], acc[2 * wp + 1][ni]);
}

// ---------------- fused MLP: 128-pt tile, streamed K chunks -------------
// smem (floats): xchunk 64x128 (32KB) | wchunk 64x128 (32KB)
//                xrbuf 128x128 (64KB) | hbuf 128x128 (64KB)  = 192KB
__global__ __launch_bounds__(512) void mlp_kernel(
    const float* __restrict__ p1, float* __restrict__ out)
{
    extern __shared__ __align__(16) float smem[];
    float* xchunk = smem;            // 8192
    float* wchunk = smem + 8192;     // 8192
    float* xrbuf  = smem + 16384;    // 16384
    float* hbuf   = smem + 32768;    // 16384

    int b   = blockIdx.y;
    int n0  = blockIdx.x * NT;
    int tid = threadIdx.x;
    int wid = tid >> 5, lane = tid & 31;
    int o   = wid * 8;
    int nn  = lane * 4;

    // persistent interp state: this thread handles point `ipt`, channels
    // [part*16, part*16+16) of each 64-ch chunk.
    int ipt  = tid >> 2;           // 0..127
    int part = tid & 3;            // 0..3
    size_t gi = ((size_t)b * NN_ + n0 + ipt) * 4;
    int4   jj = *(const int4*)(g_idx4 + gi);
    float4 ww = *(const float4*)(g_w4 + gi);
    const float4* ra = (const float4*)(g_p2t + ((size_t)b * SS + jj.x) * 256) + part * 4;
    const float4* rb = (const float4*)(g_p2t + ((size_t)b * SS + jj.y) * 256) + part * 4;
    const float4* rc = (const float4*)(g_p2t + ((size_t)b * SS + jj.z) * 256) + part * 4;
    const float4* rd = (const float4*)(g_p2t + ((size_t)b * SS + jj.w) * 256) + part * 4;

    unsigned long long acc2[4][4];
    zero_acc(acc2);

    const float4* wsrcF = (const float4*)g_Wft;   // 12288 float4
    const float4* w1F   = (const float4*)g_W1t;   // 4096
    const float4* w2F   = (const float4*)g_W2t;

    // prefetch chunk 0 (w + p1 rows 0..63)
    float4 pw[4], px[4];
#pragma unroll
    for (int i = 0; i < 4; i++) {
        int idx = tid + i * 512;
        pw[i] = wsrcF[idx];
        int row = idx >> 5, c4 = idx & 31;
        px[i] = *(const float4*)(p1 + ((size_t)b * 128 + row) * NN_ + n0 + c4 * 4);
    }

    // --- fuse GEMM: K=384 in 6 chunks of 64 ---
    for (int j = 0; j < 6; j++) {
        if (j) __syncthreads();          // previous gemm done with buffers
#pragma unroll
        for (int i = 0; i < 4; i++)
            ((float4*)wchunk)[tid + i * 512] = pw[i];
        if (j < 2) {
#pragma unroll
            for (int i = 0; i < 4; i++)
                ((float4*)xchunk)[tid + i * 512] = px[i];
        } else {
            // interp chunk: channels [ (j-2)*64, +64 ) of p2t
            int jc = j - 2;
#pragma unroll
            for (int i = 0; i < 4; i++) {
                float4 a  = ra[jc * 16 + i];
                float4 bb = rb[jc * 16 + i];
                float4 cc = rc[jc * 16 + i];
                float4 dd = rd[jc * 16 + i];
                float v0 = fmaf(ww.w, dd.x, fmaf(ww.z, cc.x, fmaf(ww.y, bb.x, ww.x * a.x)));
                float v1 = fmaf(ww.w, dd.y, fmaf(ww.z, cc.y, fmaf(ww.y, bb.y, ww.x * a.y)));
                float v2 = fmaf(ww.w, dd.z, fmaf(ww.z, cc.z, fmaf(ww.y, bb.z, ww.x * a.z)));
                float v3 = fmaf(ww.w, dd.w, fmaf(ww.z, cc.w, fmaf(ww.y, bb.w, ww.x * a.w)));
                int r0w = part * 16 + i * 4;
                xchunk[(r0w + 0) * NT + ipt] = v0;
                xchunk[(r0w + 1) * NT + ipt] = v1;
                xchunk[(r0w + 2) * NT + ipt] = v2;
                xchunk[(r0w + 3) * NT + ipt] = v3;
            }
        }
        __syncthreads();
        if (j < 5) {                     // prefetch next chunk during gemm
#pragma unroll
            for (int i = 0; i < 4; i++)
                pw[i] = wsrcF[(j + 1) * 2048 + tid + i * 512];
            if (j + 1 < 2) {
#pragma unroll
                for (int i = 0; i < 4; i++) {
                    int idx = tid + i * 512;
                    int row = idx >> 5, c4 = idx & 31;
                    px[i] = *(const float4*)(p1 + ((size_t)b * 128 + 64 * (j + 1) + row) * NN_ + n0 + c4 * 4);
                }
            }
        }
        gemm_chunk(wchunk, xchunk, o, nn, acc2);
    }

    // --- fuse epilogue: x = relu(bn_f(acc)) -> xrbuf (residual kept there) ---
    {
        float acc[8][4];
        unpack_acc(acc2, acc);
        float4 s0 = *(const float4*)(g_scale_f + o);
        float4 s1 = *(const float4*)(g_scale_f + o + 4);
        float4 t0 = *(const float4*)(g_bias_f + o);
        float4 t1 = *(const float4*)(g_bias_f + o + 4);
        float sv[8] = {s0.x, s0.y, s0.z, s0.w, s1.x, s1.y, s1.z, s1.w};
        float tv[8] = {t0.x, t0.y, t0.z, t0.w, t1.x, t1.y, t1.z, t1.w};
#pragma unroll
        for (int oi = 0; oi < 8; oi++) {
            float4 xr;
            xr.x = fmaxf(fmaf(sv[oi], acc[oi][0], tv[oi]), 0.0f);
            xr.y = fmaxf(fmaf(sv[oi], acc[oi][1], tv[oi]), 0.0f);
            xr.z = fmaxf(fmaf(sv[oi], acc[oi][2], tv[oi]), 0.0f);
            xr.w = fmaxf(fmaf(sv[oi], acc[oi][3], tv[oi]), 0.0f);
            *(float4*)(xrbuf + (o + oi) * NT + nn) = xr;
        }
    }

    // --- c1: h = relu(bn1(W1 x)), K=128 in 2 chunks ---
    zero_acc(acc2);
    for (int c = 0; c < 2; c++) {
        __syncthreads();                 // xrbuf stores (c=0) / prev gemm done
#pragma unroll
        for (int i = 0; i < 4; i++)
            ((float4*)wchunk)[tid + i * 512] = w1F[c * 2048 + tid + i * 512];
        __syncthreads();
        gemm_chunk(wchunk, xrbuf + c * 64 * NT, o, nn, acc2);
    }
    {
        float acc[8][4];
        unpack_acc(acc2, acc);
        float4 s0 = *(const float4*)(g_scale_1 + o);
        float4 s1 = *(const float4*)(g_scale_1 + o + 4);
        float4 t0 = *(const float4*)(g_bias_1 + o);
        float4 t1 = *(const float4*)(g_bias_1 + o + 4);
        float sv[8] = {s0.x, s0.y, s0.z, s0.w, s1.x, s1.y, s1.z, s1.w};
        float tv[8] = {t0.x, t0.y, t0.z, t0.w, t1.x, t1.y, t1.z, t1.w};
#pragma unroll
        for (int oi = 0; oi < 8; oi++) {
            float4 hv;
            hv.x = fmaxf(fmaf(sv[oi], acc[oi][0], tv[oi]), 0.0f);
            hv.y = fmaxf(fmaf(sv[oi], acc[oi][1], tv[oi]), 0.0f);
            hv.z = fmaxf(fmaf(sv[oi], acc[oi][2], tv[oi]), 0.0f);
            hv.w = fmaxf(fmaf(sv[oi], acc[oi][3], tv[oi]), 0.0f);
            *(float4*)(hbuf + (o + oi) * NT + nn) = hv;
        }
    }

    // --- c2 + residual: out = relu(bn2(W2 h) + x), K=128 in 2 chunks ---
    zero_acc(acc2);
    for (int c = 0; c < 2; c++) {
        __syncthreads();                 // hbuf stores (c=0) / prev gemm done
#pragma unroll
        for (int i = 0; i < 4; i++)
            ((float4*)wchunk)[tid + i * 512] = w2F[c * 2048 + tid + i * 512];
        __syncthreads();
        gemm_chunk(wchunk, hbuf + c * 64 * NT, o, nn, acc2);
    }
    {
        float acc[8][4];
        unpack_acc(acc2, acc);
        float4 s0 = *(const float4*)(g_scale_2 + o);
        float4 s1 = *(const float4*)(g_scale_2 + o + 4);
        float4 t0 = *(const float4*)(g_bias_2 + o);
        float4 t1 = *(const float4*)(g_bias_2 + o + 4);
        float sv[8] = {s0.x, s0.y, s0.z, s0.w, s1.x, s1.y, s1.z, s1.w};
        float tv[8] = {t0.x, t0.y, t0.z, t0.w, t1.x, t1.y, t1.z, t1.w};
#pragma unroll
        for (int oi = 0; oi < 8; oi++) {
            float4 xr = *(const float4*)(xrbuf + (o + oi) * NT + nn);
            float* op = out + ((size_t)b * 128 + o + oi) * NN_ + n0 + nn;
            *(float4*)op = make_float4(
                fmaxf(fmaf(sv[oi], acc[oi][0], tv[oi]) + xr.x, 0.0f),
                fmaxf(fmaf(sv[oi], acc[oi][1], tv[oi]) + xr.y, 0.0f),
                fmaxf(fmaf(sv[oi], acc[oi][2], tv[oi]) + xr.z, 0.0f),
                fmaxf(fmaf(sv[oi], acc[oi][3], tv[oi]) + xr.w, 0.0f));
        }
    }
}

// ---------------- launch ----------------
extern "C" void kernel_launch(void* const* d_in, const int* in_sizes, int n_in,
                              void* d_out, int out_size)
{
    const float* xyz1      = (const float*)d_in[0];
    const float* xyz2      = (const float*)d_in[1];
    const float* points1   = (const float*)d_in[2];
    const float* points2   = (const float*)d_in[3];
    const float* fuse_w    = (const float*)d_in[4];
    const float* fuse_b    = (const float*)d_in[5];
    const float* fuse_g    = (const float*)d_in[6];
    const float* fuse_beta = (const float*)d_in[7];
    const float* fuse_m    = (const float*)d_in[8];
    const float* fuse_v    = (const float*)d_in[9];
    const float* c1_w      = (const float*)d_in[10];
    const float* c1_b      = (const float*)d_in[11];
    const float* bn1_g     = (const float*)d_in[12];
    const float* bn1_b     = (const float*)d_in[13];
    const float* bn1_m     = (const float*)d_in[14];
    const float* bn1_v     = (const float*)d_in[15];
    const float* c2_w      = (const float*)d_in[16];
    const float* c2_b      = (const float*)d_in[17];
    const float* bn2_g     = (const float*)d_in[18];
    const float* bn2_b     = (const float*)d_in[19];
    const float* bn2_m     = (const float*)d_in[20];
    const float* bn2_v     = (const float*)d_in[21];
    float* out = (float*)d_out;

    cudaFuncSetAttribute(mlp_kernel,
                         cudaFuncAttributeMaxDynamicSharedMemorySize, 196608);

    prep_kernel<<<128, 256>>>(fuse_w, fuse_b, fuse_g, fuse_beta, fuse_m, fuse_v,
                              c1_w, c1_b, bn1_g, bn1_b, bn1_m, bn1_v,
                              c2_w, c2_b, bn2_g, bn2_b, bn2_m, bn2_v);
    transpose_kernel<<<dim3(SS / 32, 256 / 32, BB), dim3(32, 8)>>>(points2);
    knn_kernel<<<dim3(NN_ / 256, BB), 256>>>(xyz1, xyz2);
    mlp_kernel<<<dim3(NN_ / NT, BB), 512, 196608>>>(points1, out);
}

// round 13
// speedup vs baseline: 1.5872x; 1.2893x over previous
#include <cuda_runtime.h>
#include <float.h>

#define BB 16
#define NN_ 4096
#define SS 1024
#define NT 128   // points per block tile

// ---------------- scratch (device globals: allowed) ----------------
__device__ __align__(16) float g_Wft [384 * 128];   // [k][o] fuse weights (NO BN fold)
__device__ __align__(16) float g_W1t [128 * 128];   // [k][o]
__device__ __align__(16) float g_W2t [128 * 128];   // [k][o]
__device__ __align__(16) float g_scale_f[128], g_bias_f[128];
__device__ __align__(16) float g_scale_1[128], g_bias_1[128];
__device__ __align__(16) float g_scale_2[128], g_bias_2[128];
__device__ __align__(16) float g_Z[(size_t)BB * SS * 128];   // [b][s][o]  8 MB
__device__ __align__(16) int   g_idx4[(size_t)BB * NN_ * 4];
__device__ __align__(16) float g_w4 [(size_t)BB * NN_ * 4];

// ---------------- packed f32x2 helpers (sm_103a) ----------------
__device__ __forceinline__ unsigned long long pack2(float v)
{
    unsigned long long r;
    asm("mov.b64 %0, {%1, %1};" : "=l"(r) : "f"(v));
    return r;
}
__device__ __forceinline__ unsigned long long pack2p(float lo, float hi)
{
    unsigned long long r;
    asm("mov.b64 %0, {%1, %2};" : "=l"(r) : "f"(lo), "f"(hi));
    return r;
}
__device__ __forceinline__ void ffma2(unsigned long long& acc,
                                      unsigned long long w,
                                      unsigned long long x)
{
    asm("fma.rn.f32x2 %0, %1, %2, %3;" : "=l"(acc) : "l"(w), "l"(x), "l"(acc));
}
__device__ __forceinline__ void unpack2(unsigned long long p, float& lo, float& hi)
{
    asm("mov.b64 {%0, %1}, %2;" : "=f"(lo), "=f"(hi) : "l"(p));
}

// ---------------- prep: transpose weights; BN -> epilogue ----------------
__global__ void prep_kernel(
    const float* __restrict__ fw, const float* __restrict__ fb,
    const float* __restrict__ fg, const float* __restrict__ fbeta,
    const float* __restrict__ fm, const float* __restrict__ fv,
    const float* __restrict__ w1, const float* __restrict__ b1,
    const float* __restrict__ g1, const float* __restrict__ be1,
    const float* __restrict__ m1, const float* __restrict__ v1,
    const float* __restrict__ w2, const float* __restrict__ b2,
    const float* __restrict__ g2, const float* __restrict__ be2,
    const float* __restrict__ m2, const float* __restrict__ v2)
{
    const int total = 384 + 384 * 128 + 128 * 128 + 128 * 128;
    for (int i = blockIdx.x * blockDim.x + threadIdx.x; i < total;
         i += gridDim.x * blockDim.x) {
        int t = i;
        if (t < 384) {
            int o = t & 127, which = t >> 7;
            if (which == 0) {
                float a = fg[o] * rsqrtf(fv[o] + 1e-5f);
                g_scale_f[o] = a;
                g_bias_f[o]  = a * (fb[o] - fm[o]) + fbeta[o];
            } else if (which == 1) {
                float a = g1[o] * rsqrtf(v1[o] + 1e-5f);
                g_scale_1[o] = a;
                g_bias_1[o]  = a * (b1[o] - m1[o]) + be1[o];
            } else {
                float a = g2[o] * rsqrtf(v2[o] + 1e-5f);
                g_scale_2[o] = a;
                g_bias_2[o]  = a * (b2[o] - m2[o]) + be2[o];
            }
            continue;
        }
        t -= 384;
        if (t < 384 * 128) {               // fuse: [o][384] -> [k][o]
            int k = t >> 7, o = t & 127;
            g_Wft[k * 128 + o] = fw[o * 384 + k];
            continue;
        }
        t -= 384 * 128;
        if (t < 128 * 128) {
            int k = t >> 7, o = t & 127;
            g_W1t[k * 128 + o] = w1[o * 128 + k];
            continue;
        }
        t -= 128 * 128;
        {
            int k = t >> 7, o = t & 127;
            g_W2t[k * 128 + o] = w2[o * 128 + k];
        }
    }
}

// ---------------- 3-NN + weights: form F5 (JAX-GPU lowering) ----------
// DO NOT TOUCH: numerics verified (rel_err 9.32e-4, passing).
__global__ __launch_bounds__(256) void knn_kernel(
    const float* __restrict__ xyz1, const float* __restrict__ xyz2)
{
    __shared__ __align__(16) float4 sc[SS];
    int b = blockIdx.y;
    int n = blockIdx.x * 256 + threadIdx.x;

    const float* x2 = xyz2 + (size_t)b * SS * 3;
    for (int s = threadIdx.x; s < SS; s += 256) {
        float cx = x2[s * 3 + 0], cy = x2[s * 3 + 1], cz = x2[s * 3 + 2];
        float sq2 = __fmaf_rn(cz, cz, __fmaf_rn(cy, cy, __fmul_rn(cx, cx)));
        sc[s] = make_float4(cx, cy, cz, sq2);
    }
    __syncthreads();

    const float* q = xyz1 + ((size_t)b * NN_ + n) * 3;
    float qx = q[0], qy = q[1], qz = q[2];
    float sq1 = __fmaf_rn(qz, qz, __fmaf_rn(qy, qy, __fmul_rn(qx, qx)));

    float d0 = FLT_MAX, d1 = FLT_MAX, d2 = FLT_MAX;
    int   i0 = 0, i1 = 0, i2 = 0;

#pragma unroll 4
    for (int s = 0; s < SS; s++) {
        float4 c = sc[s];
        float dot = __fmaf_rn(qz, c.z, __fmaf_rn(qy, c.y, __fmul_rn(qx, c.x)));
        float d = __fsub_rn(__fadd_rn(sq1, c.w), __fadd_rn(dot, dot));
        if (d < d2) {
            if (d < d1) {
                d2 = d1; i2 = i1;
                if (d < d0) { d1 = d0; i1 = i0; d0 = d; i0 = s; }
                else        { d1 = d;  i1 = s; }
            } else { d2 = d; i2 = s; }
        }
    }

    float r0 = __fdiv_rn(1.0f, __fadd_rn(d0, 1e-8f));
    float r1 = __fdiv_rn(1.0f, __fadd_rn(d1, 1e-8f));
    float r2 = __fdiv_rn(1.0f, __fadd_rn(d2, 1e-8f));
    float sum = __fadd_rn(__fadd_rn(r0, r1), r2);

    size_t gi = ((size_t)b * NN_ + n) * 4;
    g_idx4[gi + 0] = i0; g_idx4[gi + 1] = i1;
    g_idx4[gi + 2] = i2; g_idx4[gi + 3] = i2;
    g_w4 [gi + 0] = __fdiv_rn(r0, sum);
    g_w4 [gi + 1] = __fdiv_rn(r1, sum);
    g_w4 [gi + 2] = __fdiv_rn(r2, sum);
    g_w4 [gi + 3] = 0.0f;
}

// ---------------- Z = Wf2' @ p2 : [b][s][128] ----------------
// Wf2 rows live at g_Wft[128..383][o].
__global__ __launch_bounds__(256) void zgemm_kernel(const float* __restrict__ p2)
{
    __shared__ __align__(16) float wch[32 * 128];
    __shared__ __align__(16) float ich[32 * 64];
    int b  = blockIdx.y;
    int s0 = blockIdx.x * 64;
    int tid = threadIdx.x;
    int o  = (tid >> 4) * 8;
    int nn = (tid & 15) * 4;

    float acc[8][4];
#pragma unroll
    for (int oi = 0; oi < 8; oi++)
#pragma unroll
        for (int ni = 0; ni < 4; ni++) acc[oi][ni] = 0.0f;

    for (int c0 = 0; c0 < 256; c0 += 32) {
        for (int i = tid; i < 32 * 128 / 4; i += 256)
            ((float4*)wch)[i] = ((const float4*)(g_Wft + (128 + c0) * 128))[i];
        for (int i = tid; i < 32 * 64 / 4; i += 256) {
            int c = i >> 4, sq = (i & 15);
            ((float4*)ich)[i] =
                *(const float4*)(p2 + ((size_t)b * 256 + c0 + c) * SS + s0 + sq * 4);
        }
        __syncthreads();
#pragma unroll 4
        for (int k = 0; k < 32; k++) {
            float4 w0 = *(const float4*)(wch + k * 128 + o);
            float4 w1 = *(const float4*)(wch + k * 128 + o + 4);
            float4 xv = *(const float4*)(ich + k * 64 + nn);
            float wv[8] = {w0.x, w0.y, w0.z, w0.w, w1.x, w1.y, w1.z, w1.w};
            float xa[4] = {xv.x, xv.y, xv.z, xv.w};
#pragma unroll
            for (int oi = 0; oi < 8; oi++)
#pragma unroll
                for (int ni = 0; ni < 4; ni++)
                    acc[oi][ni] = fmaf(wv[oi], xa[ni], acc[oi][ni]);
        }
        __syncthreads();
    }
#pragma unroll
    for (int ni = 0; ni < 4; ni++) {
        float* zp = g_Z + ((size_t)b * SS + s0 + nn + ni) * 128 + o;
        *(float4*)(zp)     = make_float4(acc[0][ni], acc[1][ni], acc[2][ni], acc[3][ni]);
        *(float4*)(zp + 4) = make_float4(acc[4][ni], acc[5][ni], acc[6][ni], acc[7][ni]);
    }
}

// ---------------- packed GEMM 64-k chunk (FFMA2, 8o x 4n per thread) -----
__device__ __forceinline__ void gemm_chunk(const float* __restrict__ wb,
                                           const float* __restrict__ xb,
                                           int o, int nn,
                                           unsigned long long acc2[4][4])
{
#pragma unroll 4
    for (int k = 0; k < 64; k++) {
        ulonglong2 wA = *(const ulonglong2*)(wb + k * 128 + o);
        ulonglong2 wB = *(const ulonglong2*)(wb + k * 128 + o + 4);
        float4 xv = *(const float4*)(xb + k * NT + nn);
        unsigned long long x0 = pack2(xv.x), x1 = pack2(xv.y);
        unsigned long long x2 = pack2(xv.z), x3 = pack2(xv.w);
        ffma2(acc2[0][0], wA.x, x0); ffma2(acc2[0][1], wA.x, x1);
        ffma2(acc2[0][2], wA.x, x2); ffma2(acc2[0][3], wA.x, x3);
        ffma2(acc2[1][0], wA.y, x0); ffma2(acc2[1][1], wA.y, x1);
        ffma2(acc2[1][2], wA.y, x2); ffma2(acc2[1][3], wA.y, x3);
        ffma2(acc2[2][0], wB.x, x0); ffma2(acc2[2][1], wB.x, x1);
        ffma2(acc2[2][2], wB.x, x2); ffma2(acc2[2][3], wB.x, x3);
        ffma2(acc2[3][0], wB.y, x0); ffma2(acc2[3][1], wB.y, x1);
        ffma2(acc2[3][2], wB.y, x2); ffma2(acc2[3][3], wB.y, x3);
    }
}

__device__ __forceinline__ void zero_acc(unsigned long long acc2[4][4])
{
#pragma unroll
    for (int wp = 0; wp < 4; wp++)
#pragma unroll
        for (int ni = 0; ni < 4; ni++) acc2[wp][ni] = 0ULL;
}

__device__ __forceinline__ void unpack_acc(const unsigned long long acc2[4][4],
                                           float acc[8][4])
{
#pragma unroll
    for (int wp = 0; wp < 4; wp++)
#pragma unroll
        for (int ni = 0; ni < 4; ni++)
            unpack2(acc2[wp][ni], acc[2 * wp][ni], acc[2 * wp + 1][ni]);
}

// ---------------- fused MLP: interpZ-init + fuse(K=128) + residual block --
// smem (floats): wbuf0 8192 | wbuf1 8192 | A 16384 (p1, later h) | B 16384 (x)
__global__ __launch_bounds__(512) void mlp_kernel(
    const float* __restrict__ p1, float* __restrict__ out)
{
    extern __shared__ __align__(16) float smem[];
    float* wbuf0 = smem;
    float* wbuf1 = smem + 8192;
    float* Abuf  = smem + 16384;
    float* Bbuf  = smem + 32768;

    int b   = blockIdx.y;
    int n0  = blockIdx.x * NT;
    int tid = threadIdx.x;
    int wid = tid >> 5, lane = tid & 31;
    int o   = wid * 8;
    int nn  = lane * 4;

    const float4* wfF = (const float4*)g_Wft;    // fuse rows 0..127
    const float4* w1F = (const float4*)g_W1t;
    const float4* w2F = (const float4*)g_W2t;

    float4 pw[4];
#pragma unroll
    for (int i = 0; i < 4; i++) pw[i] = wfF[tid + i * 512];   // fuse chunk 0

    // --- stage p1 tile [128k x 128n] into A ---
#pragma unroll
    for (int i = 0; i < 8; i++) {
        int idx = tid + i * 512;
        int row = idx >> 5, c4 = idx & 31;
        ((float4*)Abuf)[idx] =
            *(const float4*)(p1 + ((size_t)b * 128 + row) * NN_ + n0 + c4 * 4);
    }

    // --- interp-of-Z init: acc[oi][ni] = sum_i w_i * Z[j_i][o+oi] ---
    float acc[8][4];
#pragma unroll
    for (int ni = 0; ni < 4; ni++) {
        size_t gi = ((size_t)b * NN_ + n0 + nn + ni) * 4;
        int4   jj = *(const int4*)(g_idx4 + gi);
        float4 ww = *(const float4*)(g_w4 + gi);
        const float* za = g_Z + ((size_t)b * SS + jj.x) * 128 + o;
        const float* zb = g_Z + ((size_t)b * SS + jj.y) * 128 + o;
        const float* zc = g_Z + ((size_t)b * SS + jj.z) * 128 + o;
        float4 a0 = *(const float4*)(za), a1 = *(const float4*)(za + 4);
        float4 b0 = *(const float4*)(zb), b1 = *(const float4*)(zb + 4);
        float4 c0 = *(const float4*)(zc), c1 = *(const float4*)(zc + 4);
        float av[8] = {a0.x, a0.y, a0.z, a0.w, a1.x, a1.y, a1.z, a1.w};
        float bv[8] = {b0.x, b0.y, b0.z, b0.w, b1.x, b1.y, b1.z, b1.w};
        float cv[8] = {c0.x, c0.y, c0.z, c0.w, c1.x, c1.y, c1.z, c1.w};
#pragma unroll
        for (int oi = 0; oi < 8; oi++)
            acc[oi][ni] = fmaf(ww.z, cv[oi], fmaf(ww.y, bv[oi], ww.x * av[oi]));
    }
    unsigned long long acc2[4][4];
#pragma unroll
    for (int wp = 0; wp < 4; wp++)
#pragma unroll
        for (int ni = 0; ni < 4; ni++)
            acc2[wp][ni] = pack2p(acc[2 * wp][ni], acc[2 * wp + 1][ni]);

#pragma unroll
    for (int i = 0; i < 4; i++) ((float4*)wbuf0)[tid + i * 512] = pw[i];
    __syncthreads();                                     // A + wbuf0 ready

    // --- fuse chunk 0 ---
#pragma unroll
    for (int i = 0; i < 4; i++) pw[i] = wfF[2048 + tid + i * 512];  // fuse chunk 1
    gemm_chunk(wbuf0, Abuf, o, nn, acc2);
#pragma unroll
    for (int i = 0; i < 4; i++) ((float4*)wbuf1)[tid + i * 512] = pw[i];
    __syncthreads();

    // --- fuse chunk 1 ---
#pragma unroll
    for (int i = 0; i < 4; i++) pw[i] = w1F[tid + i * 512];         // c1 chunk 0
    gemm_chunk(wbuf1, Abuf + 64 * NT, o, nn, acc2);
#pragma unroll
    for (int i = 0; i < 4; i++) ((float4*)wbuf0)[tid + i * 512] = pw[i];
    __syncthreads();

    // --- fuse epilogue: x = relu(bn_f(acc)) -> B ---
    {
        unpack_acc(acc2, acc);
        float4 s0 = *(const float4*)(g_scale_f + o);
        float4 s1 = *(const float4*)(g_scale_f + o + 4);
        float4 t0 = *(const float4*)(g_bias_f + o);
        float4 t1 = *(const float4*)(g_bias_f + o + 4);
        float sv[8] = {s0.x, s0.y, s0.z, s0.w, s1.x, s1.y, s1.z, s1.w};
        float tv[8] = {t0.x, t0.y, t0.z, t0.w, t1.x, t1.y, t1.z, t1.w};
#pragma unroll
        for (int oi = 0; oi < 8; oi++) {
            float4 xr;
            xr.x = fmaxf(fmaf(sv[oi], acc[oi][0], tv[oi]), 0.0f);
            xr.y = fmaxf(fmaf(sv[oi], acc[oi][1], tv[oi]), 0.0f);
            xr.z = fmaxf(fmaf(sv[oi], acc[oi][2], tv[oi]), 0.0f);
            xr.w = fmaxf(fmaf(sv[oi], acc[oi][3], tv[oi]), 0.0f);
            *(float4*)(Bbuf + (o + oi) * NT + nn) = xr;
        }
    }
#pragma unroll
    for (int i = 0; i < 4; i++) pw[i] = w1F[2048 + tid + i * 512];  // c1 chunk 1
    __syncthreads();                                     // B visible

    // --- c1 chunk 0 ---
    zero_acc(acc2);
    gemm_chunk(wbuf0, Bbuf, o, nn, acc2);
#pragma unroll
    for (int i = 0; i < 4; i++) ((float4*)wbuf1)[tid + i * 512] = pw[i];
    __syncthreads();

    // --- c1 chunk 1 ---
#pragma unroll
    for (int i = 0; i < 4; i++) pw[i] = w2F[tid + i * 512];         // c2 chunk 0
    gemm_chunk(wbuf1, Bbuf + 64 * NT, o, nn, acc2);
#pragma unroll
    for (int i = 0; i < 4; i++) ((float4*)wbuf0)[tid + i * 512] = pw[i];
    __syncthreads();

    // --- c1 epilogue: h = relu(bn1(acc)) -> A (p1 dead) ---
    {
        unpack_acc(acc2, acc);
        float4 s0 = *(const float4*)(g_scale_1 + o);
        float4 s1 = *(const float4*)(g_scale_1 + o + 4);
        float4 t0 = *(const float4*)(g_bias_1 + o);
        float4 t1 = *(const float4*)(g_bias_1 + o + 4);
        float sv[8] = {s0.x, s0.y, s0.z, s0.w, s1.x, s1.y, s1.z, s1.w};
        float tv[8] = {t0.x, t0.y, t0.z, t0.w, t1.x, t1.y, t1.z, t1.w};
#pragma unroll
        for (int oi = 0; oi < 8; oi++) {
            float4 hv;
            hv.x = fmaxf(fmaf(sv[oi], acc[oi][0], tv[oi]), 0.0f);
            hv.y = fmaxf(fmaf(sv[oi], acc[oi][1], tv[oi]), 0.0f);
            hv.z = fmaxf(fmaf(sv[oi], acc[oi][2], tv[oi]), 0.0f);
            hv.w = fmaxf(fmaf(sv[oi], acc[oi][3], tv[oi]), 0.0f);
            *(float4*)(Abuf + (o + oi) * NT + nn) = hv;
        }
    }
#pragma unroll
    for (int i = 0; i < 4; i++) pw[i] = w2F[2048 + tid + i * 512];  // c2 chunk 1
    __syncthreads();                                     // A(h) visible

    // --- c2 chunk 0 ---
    zero_acc(acc2);
    gemm_chunk(wbuf0, Abuf, o, nn, acc2);
#pragma unroll
    for (int i = 0; i < 4; i++) ((float4*)wbuf1)[tid + i * 512] = pw[i];
    __syncthreads();

    // --- c2 chunk 1 ---
    gemm_chunk(wbuf1, Abuf + 64 * NT, o, nn, acc2);

    // --- c2 epilogue: out = relu(bn2(acc) + x) ---
    {
        unpack_acc(acc2, acc);
        float4 s0 = *(const float4*)(g_scale_2 + o);
        float4 s1 = *(const float4*)(g_scale_2 + o + 4);
        float4 t0 = *(const float4*)(g_bias_2 + o);
        float4 t1 = *(const float4*)(g_bias_2 + o + 4);
        float sv[8] = {s0.x, s0.y, s0.z, s0.w, s1.x, s1.y, s1.z, s1.w};
        float tv[8] = {t0.x, t0.y, t0.z, t0.w, t1.x, t1.y, t1.z, t1.w};
#pragma unroll
        for (int oi = 0; oi < 8; oi++) {
            float4 xr = *(const float4*)(Bbuf + (o + oi) * NT + nn);
            float* op = out + ((size_t)b * 128 + o + oi) * NN_ + n0 + nn;
            *(float4*)op = make_float4(
                fmaxf(fmaf(sv[oi], acc[oi][0], tv[oi]) + xr.x, 0.0f),
                fmaxf(fmaf(sv[oi], acc[oi][1], tv[oi]) + xr.y, 0.0f),
                fmaxf(fmaf(sv[oi], acc[oi][2], tv[oi]) + xr.z, 0.0f),
                fmaxf(fmaf(sv[oi], acc[oi][3], tv[oi]) + xr.w, 0.0f));
        }
    }
}

// ---------------- launch ----------------
extern "C" void kernel_launch(void* const* d_in, const int* in_sizes, int n_in,
                              void* d_out, int out_size)
{
    const float* xyz1      = (const float*)d_in[0];
    const float* xyz2      = (const float*)d_in[1];
    const float* points1   = (const float*)d_in[2];
    const float* points2   = (const float*)d_in[3];
    const float* fuse_w    = (const float*)d_in[4];
    const float* fuse_b    = (const float*)d_in[5];
    const float* fuse_g    = (const float*)d_in[6];
    const float* fuse_beta = (const float*)d_in[7];
    const float* fuse_m    = (const float*)d_in[8];
    const float* fuse_v    = (const float*)d_in[9];
    const float* c1_w      = (const float*)d_in[10];
    const float* c1_b      = (const float*)d_in[11];
    const float* bn1_g     = (const float*)d_in[12];
    const float* bn1_b     = (const float*)d_in[13];
    const float* bn1_m     = (const float*)d_in[14];
    const float* bn1_v     = (const float*)d_in[15];
    const float* c2_w      = (const float*)d_in[16];
    const float* c2_b      = (const float*)d_in[17];
    const float* bn2_g     = (const float*)d_in[18];
    const float* bn2_b     = (const float*)d_in[19];
    const float* bn2_m     = (const float*)d_in[20];
    const float* bn2_v     = (const float*)d_in[21];
    float* out = (float*)d_out;

    cudaFuncSetAttribute(mlp_kernel,
                         cudaFuncAttributeMaxDynamicSharedMemorySize, 196608);

    prep_kernel<<<128, 256>>>(fuse_w, fuse_b, fuse_g, fuse_beta, fuse_m, fuse_v,
                              c1_w, c1_b, bn1_g, bn1_b, bn1_m, bn1_v,
                              c2_w, c2_b, bn2_g, bn2_b, bn2_m, bn2_v);
    knn_kernel<<<dim3(NN_ / 256, BB), 256>>>(xyz1, xyz2);
    zgemm_kernel<<<dim3(SS / 64, BB), 256>>>(points2);
    mlp_kernel<<<dim3(NN_ / NT, BB), 512, 196608>>>(points1, out);
}

// round 14
// speedup vs baseline: 1.6030x; 1.0099x over previous
#include <cuda_runtime.h>
#include <float.h>

#define BB 16
#define NN_ 4096
#define SS 1024
#define NT 128   // points per block tile

// ---------------- scratch (device globals: allowed) ----------------
__device__ __align__(16) float g_Wft [384 * 128];   // [k][o] fuse weights (NO BN fold)
__device__ __align__(16) float g_W1t [128 * 128];   // [k][o]
__device__ __align__(16) float g_W2t [128 * 128];   // [k][o]
__device__ __align__(16) float g_scale_f[128], g_bias_f[128];
__device__ __align__(16) float g_scale_1[128], g_bias_1[128];
__device__ __align__(16) float g_scale_2[128], g_bias_2[128];
__device__ __align__(16) float g_Z[(size_t)BB * SS * 128];   // [b][s][o]  8 MB
__device__ __align__(16) int   g_idx4[(size_t)BB * NN_ * 4];
__device__ __align__(16) float g_w4 [(size_t)BB * NN_ * 4];

// ---------------- packed f32x2 helpers (sm_103a) ----------------
__device__ __forceinline__ unsigned long long pack2(float v)
{
    unsigned long long r;
    asm("mov.b64 %0, {%1, %1};" : "=l"(r) : "f"(v));
    return r;
}
__device__ __forceinline__ unsigned long long pack2p(float lo, float hi)
{
    unsigned long long r;
    asm("mov.b64 %0, {%1, %2};" : "=l"(r) : "f"(lo), "f"(hi));
    return r;
}
__device__ __forceinline__ void ffma2(unsigned long long& acc,
                                      unsigned long long w,
                                      unsigned long long x)
{
    asm("fma.rn.f32x2 %0, %1, %2, %3;" : "=l"(acc) : "l"(w), "l"(x), "l"(acc));
}
__device__ __forceinline__ void unpack2(unsigned long long p, float& lo, float& hi)
{
    asm("mov.b64 {%0, %1}, %2;" : "=f"(lo), "=f"(hi) : "l"(p));
}

// ---------------- prep: transpose weights; BN -> epilogue ----------------
__global__ void prep_kernel(
    const float* __restrict__ fw, const float* __restrict__ fb,
    const float* __restrict__ fg, const float* __restrict__ fbeta,
    const float* __restrict__ fm, const float* __restrict__ fv,
    const float* __restrict__ w1, const float* __restrict__ b1,
    const float* __restrict__ g1, const float* __restrict__ be1,
    const float* __restrict__ m1, const float* __restrict__ v1,
    const float* __restrict__ w2, const float* __restrict__ b2,
    const float* __restrict__ g2, const float* __restrict__ be2,
    const float* __restrict__ m2, const float* __restrict__ v2)
{
    const int total = 384 + 384 * 128 + 128 * 128 + 128 * 128;
    for (int i = blockIdx.x * blockDim.x + threadIdx.x; i < total;
         i += gridDim.x * blockDim.x) {
        int t = i;
        if (t < 384) {
            int o = t & 127, which = t >> 7;
            if (which == 0) {
                float a = fg[o] * rsqrtf(fv[o] + 1e-5f);
                g_scale_f[o] = a;
                g_bias_f[o]  = a * (fb[o] - fm[o]) + fbeta[o];
            } else if (which == 1) {
                float a = g1[o] * rsqrtf(v1[o] + 1e-5f);
                g_scale_1[o] = a;
                g_bias_1[o]  = a * (b1[o] - m1[o]) + be1[o];
            } else {
                float a = g2[o] * rsqrtf(v2[o] + 1e-5f);
                g_scale_2[o] = a;
                g_bias_2[o]  = a * (b2[o] - m2[o]) + be2[o];
            }
            continue;
        }
        t -= 384;
        if (t < 384 * 128) {               // fuse: [o][384] -> [k][o]
            int k = t >> 7, o = t & 127;
            g_Wft[k * 128 + o] = fw[o * 384 + k];
            continue;
        }
        t -= 384 * 128;
        if (t < 128 * 128) {
            int k = t >> 7, o = t & 127;
            g_W1t[k * 128 + o] = w1[o * 128 + k];
            continue;
        }
        t -= 128 * 128;
        {
            int k = t >> 7, o = t & 127;
            g_W2t[k * 128 + o] = w2[o * 128 + k];
        }
    }
}

// ---------------- merged knn (z=0) + zgemm (z=1) ----------------
// knn numerics (form F5): DO NOT TOUCH — verified rel_err 9.32e-4.
__global__ __launch_bounds__(256) void knn_zgemm_kernel(
    const float* __restrict__ xyz1, const float* __restrict__ xyz2,
    const float* __restrict__ p2)
{
    __shared__ __align__(16) float sbuf[6144];   // 24KB union

    if (blockIdx.z == 0) {
        // ---------------- 3-NN + weights ----------------
        float4* sc = (float4*)sbuf;              // 1024 float4 = 16KB
        int b = blockIdx.y;
        int n = blockIdx.x * 256 + threadIdx.x;

        const float* x2 = xyz2 + (size_t)b * SS * 3;
        for (int s = threadIdx.x; s < SS; s += 256) {
            float cx = x2[s * 3 + 0], cy = x2[s * 3 + 1], cz = x2[s * 3 + 2];
            float sq2 = __fmaf_rn(cz, cz, __fmaf_rn(cy, cy, __fmul_rn(cx, cx)));
            sc[s] = make_float4(cx, cy, cz, sq2);
        }
        __syncthreads();

        const float* q = xyz1 + ((size_t)b * NN_ + n) * 3;
        float qx = q[0], qy = q[1], qz = q[2];
        float sq1 = __fmaf_rn(qz, qz, __fmaf_rn(qy, qy, __fmul_rn(qx, qx)));

        float d0 = FLT_MAX, d1 = FLT_MAX, d2 = FLT_MAX;
        int   i0 = 0, i1 = 0, i2 = 0;

#pragma unroll 4
        for (int s = 0; s < SS; s++) {
            float4 c = sc[s];
            float dot = __fmaf_rn(qz, c.z, __fmaf_rn(qy, c.y, __fmul_rn(qx, c.x)));
            float d = __fsub_rn(__fadd_rn(sq1, c.w), __fadd_rn(dot, dot));
            if (d < d2) {
                if (d < d1) {
                    d2 = d1; i2 = i1;
                    if (d < d0) { d1 = d0; i1 = i0; d0 = d; i0 = s; }
                    else        { d1 = d;  i1 = s; }
                } else { d2 = d; i2 = s; }
            }
        }

        float r0 = __fdiv_rn(1.0f, __fadd_rn(d0, 1e-8f));
        float r1 = __fdiv_rn(1.0f, __fadd_rn(d1, 1e-8f));
        float r2 = __fdiv_rn(1.0f, __fadd_rn(d2, 1e-8f));
        float sum = __fadd_rn(__fadd_rn(r0, r1), r2);

        size_t gi = ((size_t)b * NN_ + n) * 4;
        g_idx4[gi + 0] = i0; g_idx4[gi + 1] = i1;
        g_idx4[gi + 2] = i2; g_idx4[gi + 3] = i2;
        g_w4 [gi + 0] = __fdiv_rn(r0, sum);
        g_w4 [gi + 1] = __fdiv_rn(r1, sum);
        g_w4 [gi + 2] = __fdiv_rn(r2, sum);
        g_w4 [gi + 3] = 0.0f;
    } else {
        // ---------------- Z = Wf2' @ p2 : [b][s][128] ----------------
        float* wch = sbuf;                       // 32*128 = 16KB
        float* ich = sbuf + 4096;                // 32*64  = 8KB
        int b  = blockIdx.y;
        int s0 = blockIdx.x * 64;
        int tid = threadIdx.x;
        int o  = (tid >> 4) * 8;
        int nn = (tid & 15) * 4;

        float acc[8][4];
#pragma unroll
        for (int oi = 0; oi < 8; oi++)
#pragma unroll
            for (int ni = 0; ni < 4; ni++) acc[oi][ni] = 0.0f;

        for (int c0 = 0; c0 < 256; c0 += 32) {
            for (int i = tid; i < 32 * 128 / 4; i += 256)
                ((float4*)wch)[i] = ((const float4*)(g_Wft + (128 + c0) * 128))[i];
            for (int i = tid; i < 32 * 64 / 4; i += 256) {
                int c = i >> 4, sq = (i & 15);
                ((float4*)ich)[i] =
                    *(const float4*)(p2 + ((size_t)b * 256 + c0 + c) * SS + s0 + sq * 4);
            }
            __syncthreads();
#pragma unroll 4
            for (int k = 0; k < 32; k++) {
                float4 w0 = *(const float4*)(wch + k * 128 + o);
                float4 w1 = *(const float4*)(wch + k * 128 + o + 4);
                float4 xv = *(const float4*)(ich + k * 64 + nn);
                float wv[8] = {w0.x, w0.y, w0.z, w0.w, w1.x, w1.y, w1.z, w1.w};
                float xa[4] = {xv.x, xv.y, xv.z, xv.w};
#pragma unroll
                for (int oi = 0; oi < 8; oi++)
#pragma unroll
                    for (int ni = 0; ni < 4; ni++)
                        acc[oi][ni] = fmaf(wv[oi], xa[ni], acc[oi][ni]);
            }
            __syncthreads();
        }
#pragma unroll
        for (int ni = 0; ni < 4; ni++) {
            float* zp = g_Z + ((size_t)b * SS + s0 + nn + ni) * 128 + o;
            *(float4*)(zp)     = make_float4(acc[0][ni], acc[1][ni], acc[2][ni], acc[3][ni]);
            *(float4*)(zp + 4) = make_float4(acc[4][ni], acc[5][ni], acc[6][ni], acc[7][ni]);
        }
    }
}

// ---------------- packed GEMM 64-k chunk (FFMA2, 2-D warp tiling) --------
// Warp covers 32o x 32n; per k per warp: 2 w-LDS (64B each, conflict-free)
// + 1 x-LDS (128B, 4-lane broadcast) = 3 wavefronts.
// Bit-exact: one fp32 FMA per output per k, k ascending.
__device__ __forceinline__ void gemm_chunk(const float* __restrict__ wb,
                                           const float* __restrict__ xb,
                                           int o, int nn,
                                           unsigned long long acc2[4][4])
{
#pragma unroll 4
    for (int k = 0; k < 64; k++) {
        ulonglong2 wA = *(const ulonglong2*)(wb + k * 128 + o);
        ulonglong2 wB = *(const ulonglong2*)(wb + k * 128 + o + 4);
        float4 xv = *(const float4*)(xb + k * NT + nn);
        unsigned long long x0 = pack2(xv.x), x1 = pack2(xv.y);
        unsigned long long x2 = pack2(xv.z), x3 = pack2(xv.w);
        ffma2(acc2[0][0], wA.x, x0); ffma2(acc2[0][1], wA.x, x1);
        ffma2(acc2[0][2], wA.x, x2); ffma2(acc2[0][3], wA.x, x3);
        ffma2(acc2[1][0], wA.y, x0); ffma2(acc2[1][1], wA.y, x1);
        ffma2(acc2[1][2], wA.y, x2); ffma2(acc2[1][3], wA.y, x3);
        ffma2(acc2[2][0], wB.x, x0); ffma2(acc2[2][1], wB.x, x1);
        ffma2(acc2[2][2], wB.x, x2); ffma2(acc2[2][3], wB.x, x3);
        ffma2(acc2[3][0], wB.y, x0); ffma2(acc2[3][1], wB.y, x1);
        ffma2(acc2[3][2], wB.y, x2); ffma2(acc2[3][3], wB.y, x3);
    }
}

__device__ __forceinline__ void zero_acc(unsigned long long acc2[4][4])
{
#pragma unroll
    for (int wp = 0; wp < 4; wp++)
#pragma unroll
        for (int ni = 0; ni < 4; ni++) acc2[wp][ni] = 0ULL;
}

__device__ __forceinline__ void unpack_acc(const unsigned long long acc2[4][4],
                                           float acc[8][4])
{
#pragma unroll
    for (int wp = 0; wp < 4; wp++)
#pragma unroll
        for (int ni = 0; ni < 4; ni++)
            unpack2(acc2[wp][ni], acc[2 * wp][ni], acc[2 * wp + 1][ni]);
}

// ---------------- fused MLP: interpZ-init + fuse(K=128) + residual block --
// smem (floats): wbuf0 8192 | wbuf1 8192 | A 16384 (p1, later h) | B 16384 (x)
__global__ __launch_bounds__(512) void mlp_kernel(
    const float* __restrict__ p1, float* __restrict__ out)
{
    extern __shared__ __align__(16) float smem[];
    float* wbuf0 = smem;
    float* wbuf1 = smem + 8192;
    float* Abuf  = smem + 16384;
    float* Bbuf  = smem + 32768;

    int b   = blockIdx.y;
    int n0  = blockIdx.x * NT;
    int tid = threadIdx.x;
    int wid = tid >> 5, lane = tid & 31;
    // 2-D warp tiling: warp (wid&3, wid>>2) covers 32o x 32n
    int o   = (wid & 3) * 32 + (lane & 3) * 8;
    int nn  = (wid >> 2) * 32 + (lane >> 2) * 4;

    const float4* wfF = (const float4*)g_Wft;    // fuse rows 0..127
    const float4* w1F = (const float4*)g_W1t;
    const float4* w2F = (const float4*)g_W2t;

    float4 pw[4];
#pragma unroll
    for (int i = 0; i < 4; i++) pw[i] = wfF[tid + i * 512];   // fuse chunk 0

    // --- stage p1 tile [128k x 128n] into A ---
#pragma unroll
    for (int i = 0; i < 8; i++) {
        int idx = tid + i * 512;
        int row = idx >> 5, c4 = idx & 31;
        ((float4*)Abuf)[idx] =
            *(const float4*)(p1 + ((size_t)b * 128 + row) * NN_ + n0 + c4 * 4);
    }

    // --- interp-of-Z init: acc[oi][ni] = sum_i w_i * Z[j_i][o+oi] ---
    float acc[8][4];
#pragma unroll
    for (int ni = 0; ni < 4; ni++) {
        size_t gi = ((size_t)b * NN_ + n0 + nn + ni) * 4;
        int4   jj = *(const int4*)(g_idx4 + gi);
        float4 ww = *(const float4*)(g_w4 + gi);
        const float* za = g_Z + ((size_t)b * SS + jj.x) * 128 + o;
        const float* zb = g_Z + ((size_t)b * SS + jj.y) * 128 + o;
        const float* zc = g_Z + ((size_t)b * SS + jj.z) * 128 + o;
        float4 a0 = *(const float4*)(za), a1 = *(const float4*)(za + 4);
        float4 b0 = *(const float4*)(zb), b1 = *(const float4*)(zb + 4);
        float4 c0 = *(const float4*)(zc), c1 = *(const float4*)(zc + 4);
        float av[8] = {a0.x, a0.y, a0.z, a0.w, a1.x, a1.y, a1.z, a1.w};
        float bv[8] = {b0.x, b0.y, b0.z, b0.w, b1.x, b1.y, b1.z, b1.w};
        float cv[8] = {c0.x, c0.y, c0.z, c0.w, c1.x, c1.y, c1.z, c1.w};
#pragma unroll
        for (int oi = 0; oi < 8; oi++)
            acc[oi][ni] = fmaf(ww.z, cv[oi], fmaf(ww.y, bv[oi], ww.x * av[oi]));
    }
    unsigned long long acc2[4][4];
#pragma unroll
    for (int wp = 0; wp < 4; wp++)
#pragma unroll
        for (int ni = 0; ni < 4; ni++)
            acc2[wp][ni] = pack2p(acc[2 * wp][ni], acc[2 * wp + 1][ni]);

#pragma unroll
    for (int i = 0; i < 4; i++) ((float4*)wbuf0)[tid + i * 512] = pw[i];
    __syncthreads();                                     // A + wbuf0 ready

    // --- fuse chunk 0 ---
#pragma unroll
    for (int i = 0; i < 4; i++) pw[i] = wfF[2048 + tid + i * 512];  // fuse chunk 1
    gemm_chunk(wbuf0, Abuf, o, nn, acc2);
#pragma unroll
    for (int i = 0; i < 4; i++) ((float4*)wbuf1)[tid + i * 512] = pw[i];
    __syncthreads();

    // --- fuse chunk 1 ---
#pragma unroll
    for (int i = 0; i < 4; i++) pw[i] = w1F[tid + i * 512];         // c1 chunk 0
    gemm_chunk(wbuf1, Abuf + 64 * NT, o, nn, acc2);
#pragma unroll
    for (int i = 0; i < 4; i++) ((float4*)wbuf0)[tid + i * 512] = pw[i];
    __syncthreads();

    // --- fuse epilogue: x = relu(bn_f(acc)) -> B ---
    {
        unpack_acc(acc2, acc);
        float4 s0 = *(const float4*)(g_scale_f + o);
        float4 s1 = *(const float4*)(g_scale_f + o + 4);
        float4 t0 = *(const float4*)(g_bias_f + o);
        float4 t1 = *(const float4*)(g_bias_f + o + 4);
        float sv[8] = {s0.x, s0.y, s0.z, s0.w, s1.x, s1.y, s1.z, s1.w};
        float tv[8] = {t0.x, t0.y, t0.z, t0.w, t1.x, t1.y, t1.z, t1.w};
#pragma unroll
        for (int oi = 0; oi < 8; oi++) {
            float4 xr;
            xr.x = fmaxf(fmaf(sv[oi], acc[oi][0], tv[oi]), 0.0f);
            xr.y = fmaxf(fmaf(sv[oi], acc[oi][1], tv[oi]), 0.0f);
            xr.z = fmaxf(fmaf(sv[oi], acc[oi][2], tv[oi]), 0.0f);
            xr.w = fmaxf(fmaf(sv[oi], acc[oi][3], tv[oi]), 0.0f);
            *(float4*)(Bbuf + (o + oi) * NT + nn) = xr;
        }
    }
#pragma unroll
    for (int i = 0; i < 4; i++) pw[i] = w1F[2048 + tid + i * 512];  // c1 chunk 1
    __syncthreads();                                     // B visible

    // --- c1 chunk 0 ---
    zero_acc(acc2);
    gemm_chunk(wbuf0, Bbuf, o, nn, acc2);
#pragma unroll
    for (int i = 0; i < 4; i++) ((float4*)wbuf1)[tid + i * 512] = pw[i];
    __syncthreads();

    // --- c1 chunk 1 ---
#pragma unroll
    for (int i = 0; i < 4; i++) pw[i] = w2F[tid + i * 512];         // c2 chunk 0
    gemm_chunk(wbuf1, Bbuf + 64 * NT, o, nn, acc2);
#pragma unroll
    for (int i = 0; i < 4; i++) ((float4*)wbuf0)[tid + i * 512] = pw[i];
    __syncthreads();

    // --- c1 epilogue: h = relu(bn1(acc)) -> A (p1 dead) ---
    {
        unpack_acc(acc2, acc);
        float4 s0 = *(const float4*)(g_scale_1 + o);
        float4 s1 = *(const float4*)(g_scale_1 + o + 4);
        float4 t0 = *(const float4*)(g_bias_1 + o);
        float4 t1 = *(const float4*)(g_bias_1 + o + 4);
        float sv[8] = {s0.x, s0.y, s0.z, s0.w, s1.x, s1.y, s1.z, s1.w};
        float tv[8] = {t0.x, t0.y, t0.z, t0.w, t1.x, t1.y, t1.z, t1.w};
#pragma unroll
        for (int oi = 0; oi < 8; oi++) {
            float4 hv;
            hv.x = fmaxf(fmaf(sv[oi], acc[oi][0], tv[oi]), 0.0f);
            hv.y = fmaxf(fmaf(sv[oi], acc[oi][1], tv[oi]), 0.0f);
            hv.z = fmaxf(fmaf(sv[oi], acc[oi][2], tv[oi]), 0.0f);
            hv.w = fmaxf(fmaf(sv[oi], acc[oi][3], tv[oi]), 0.0f);
            *(float4*)(Abuf + (o + oi) * NT + nn) = hv;
        }
    }
#pragma unroll
    for (int i = 0; i < 4; i++) pw[i] = w2F[2048 + tid + i * 512];  // c2 chunk 1
    __syncthreads();                                     // A(h) visible

    // --- c2 chunk 0 ---
    zero_acc(acc2);
    gemm_chunk(wbuf0, Abuf, o, nn, acc2);
#pragma unroll
    for (int i = 0; i < 4; i++) ((float4*)wbuf1)[tid + i * 512] = pw[i];
    __syncthreads();

    // --- c2 chunk 1 ---
    gemm_chunk(wbuf1, Abuf + 64 * NT, o, nn, acc2);

    // --- c2 epilogue: out = relu(bn2(acc) + x) ---
    {
        unpack_acc(acc2, acc);
        float4 s0 = *(const float4*)(g_scale_2 + o);
        float4 s1 = *(const float4*)(g_scale_2 + o + 4);
        float4 t0 = *(const float4*)(g_bias_2 + o);
        float4 t1 = *(const float4*)(g_bias_2 + o + 4);
        float sv[8] = {s0.x, s0.y, s0.z, s0.w, s1.x, s1.y, s1.z, s1.w};
        float tv[8] = {t0.x, t0.y, t0.z, t0.w, t1.x, t1.y, t1.z, t1.w};
#pragma unroll
        for (int oi = 0; oi < 8; oi++) {
            float4 xr = *(const float4*)(Bbuf + (o + oi) * NT + nn);
            float* op = out + ((size_t)b * 128 + o + oi) * NN_ + n0 + nn;
            *(float4*)op = make_float4(
                fmaxf(fmaf(sv[oi], acc[oi][0], tv[oi]) + xr.x, 0.0f),
                fmaxf(fmaf(sv[oi], acc[oi][1], tv[oi]) + xr.y, 0.0f),
                fmaxf(fmaf(sv[oi], acc[oi][2], tv[oi]) + xr.z, 0.0f),
                fmaxf(fmaf(sv[oi], acc[oi][3], tv[oi]) + xr.w, 0.0f));
        }
    }
}

// ---------------- launch ----------------
extern "C" void kernel_launch(void* const* d_in, const int* in_sizes, int n_in,
                              void* d_out, int out_size)
{
    const float* xyz1      = (const float*)d_in[0];
    const float* xyz2      = (const float*)d_in[1];
    const float* points1   = (const float*)d_in[2];
    const float* points2   = (const float*)d_in[3];
    const float* fuse_w    = (const float*)d_in[4];
    const float* fuse_b    = (const float*)d_in[5];
    const float* fuse_g    = (const float*)d_in[6];
    const float* fuse_beta = (const float*)d_in[7];
    const float* fuse_m    = (const float*)d_in[8];
    const float* fuse_v    = (const float*)d_in[9];
    const float* c1_w      = (const float*)d_in[10];
    const float* c1_b      = (const float*)d_in[11];
    const float* bn1_g     = (const float*)d_in[12];
    const float* bn1_b     = (const float*)d_in[13];
    const float* bn1_m     = (const float*)d_in[14];
    const float* bn1_v     = (const float*)d_in[15];
    const float* c2_w      = (const float*)d_in[16];
    const float* c2_b      = (const float*)d_in[17];
    const float* bn2_g     = (const float*)d_in[18];
    const float* bn2_b     = (const float*)d_in[19];
    const float* bn2_m     = (const float*)d_in[20];
    const float* bn2_v     = (const float*)d_in[21];
    float* out = (float*)d_out;

    cudaFuncSetAttribute(mlp_kernel,
                         cudaFuncAttributeMaxDynamicSharedMemorySize, 196608);

    prep_kernel<<<128, 256>>>(fuse_w, fuse_b, fuse_g, fuse_beta, fuse_m, fuse_v,
                              c1_w, c1_b, bn1_g, bn1_b, bn1_m, bn1_v,
                              c2_w, c2_b, bn2_g, bn2_b, bn2_m, bn2_v);
    knn_zgemm_kernel<<<dim3(16, BB, 2), 256>>>(xyz1, xyz2, points2);
    mlp_kernel<<<dim3(NN_ / NT, BB), 512, 196608>>>(points1, out);
}

// round 15
// speedup vs baseline: 1.6340x; 1.0194x over previous
#include <cuda_runtime.h>
#include <float.h>

#define BB 16
#define NN_ 4096
#define SS 1024
#define NT 128   // points per block tile

// ---------------- scratch (device globals: allowed) ----------------
__device__ __align__(16) float g_Wft [384 * 128];   // [k][o] fuse weights (NO BN fold)
__device__ __align__(16) float g_W1t [128 * 128];   // [k][o]
__device__ __align__(16) float g_W2t [128 * 128];   // [k][o]
__device__ __align__(16) float g_scale_f[128], g_bias_f[128];
__device__ __align__(16) float g_scale_1[128], g_bias_1[128];
__device__ __align__(16) float g_scale_2[128], g_bias_2[128];
__device__ __align__(16) float g_Z[(size_t)BB * SS * 128];   // [b][s][o]  8 MB
__device__ __align__(16) int   g_idx4[(size_t)BB * NN_ * 4];
__device__ __align__(16) float g_w4 [(size_t)BB * NN_ * 4];

// ---------------- packed f32x2 helpers (sm_103a) ----------------
__device__ __forceinline__ unsigned long long pack2(float v)
{
    unsigned long long r;
    asm("mov.b64 %0, {%1, %1};" : "=l"(r) : "f"(v));
    return r;
}
__device__ __forceinline__ unsigned long long pack2p(float lo, float hi)
{
    unsigned long long r;
    asm("mov.b64 %0, {%1, %2};" : "=l"(r) : "f"(lo), "f"(hi));
    return r;
}
__device__ __forceinline__ void ffma2(unsigned long long& acc,
                                      unsigned long long w,
                                      unsigned long long x)
{
    asm("fma.rn.f32x2 %0, %1, %2, %3;" : "=l"(acc) : "l"(w), "l"(x), "l"(acc));
}
__device__ __forceinline__ void unpack2(unsigned long long p, float& lo, float& hi)
{
    asm("mov.b64 {%0, %1}, %2;" : "=f"(lo), "=f"(hi) : "l"(p));
}

// ---------------- prep: transpose weights; BN -> epilogue ----------------
__global__ void prep_kernel(
    const float* __restrict__ fw, const float* __restrict__ fb,
    const float* __restrict__ fg, const float* __restrict__ fbeta,
    const float* __restrict__ fm, const float* __restrict__ fv,
    const float* __restrict__ w1, const float* __restrict__ b1,
    const float* __restrict__ g1, const float* __restrict__ be1,
    const float* __restrict__ m1, const float* __restrict__ v1,
    const float* __restrict__ w2, const float* __restrict__ b2,
    const float* __restrict__ g2, const float* __restrict__ be2,
    const float* __restrict__ m2, const float* __restrict__ v2)
{
    const int total = 384 + 384 * 128 + 128 * 128 + 128 * 128;
    for (int i = blockIdx.x * blockDim.x + threadIdx.x; i < total;
         i += gridDim.x * blockDim.x) {
        int t = i;
        if (t < 384) {
            int o = t & 127, which = t >> 7;
            if (which == 0) {
                float a = fg[o] * rsqrtf(fv[o] + 1e-5f);
                g_scale_f[o] = a;
                g_bias_f[o]  = a * (fb[o] - fm[o]) + fbeta[o];
            } else if (which == 1) {
                float a = g1[o] * rsqrtf(v1[o] + 1e-5f);
                g_scale_1[o] = a;
                g_bias_1[o]  = a * (b1[o] - m1[o]) + be1[o];
            } else {
                float a = g2[o] * rsqrtf(v2[o] + 1e-5f);
                g_scale_2[o] = a;
                g_bias_2[o]  = a * (b2[o] - m2[o]) + be2[o];
            }
            continue;
        }
        t -= 384;
        if (t < 384 * 128) {               // fuse: [o][384] -> [k][o]
            int k = t >> 7, o = t & 127;
            g_Wft[k * 128 + o] = fw[o * 384 + k];
            continue;
        }
        t -= 384 * 128;
        if (t < 128 * 128) {
            int k = t >> 7, o = t & 127;
            g_W1t[k * 128 + o] = w1[o * 128 + k];
            continue;
        }
        t -= 128 * 128;
        {
            int k = t >> 7, o = t & 127;
            g_W2t[k * 128 + o] = w2[o * 128 + k];
        }
    }
}

// ---------------- merged knn (z=0) + zgemm (z=1) ----------------
// knn numerics (form F5): DO NOT TOUCH — verified rel_err 9.32e-4.
__global__ __launch_bounds__(256) void knn_zgemm_kernel(
    const float* __restrict__ xyz1, const float* __restrict__ xyz2,
    const float* __restrict__ p2)
{
    __shared__ __align__(16) float sbuf[6144];   // 24KB union

    if (blockIdx.z == 0) {
        // ---------------- 3-NN + weights ----------------
        float4* sc = (float4*)sbuf;              // 1024 float4 = 16KB
        int b = blockIdx.y;
        int n = blockIdx.x * 256 + threadIdx.x;

        const float* x2 = xyz2 + (size_t)b * SS * 3;
        for (int s = threadIdx.x; s < SS; s += 256) {
            float cx = x2[s * 3 + 0], cy = x2[s * 3 + 1], cz = x2[s * 3 + 2];
            float sq2 = __fmaf_rn(cz, cz, __fmaf_rn(cy, cy, __fmul_rn(cx, cx)));
            sc[s] = make_float4(cx, cy, cz, sq2);
        }
        __syncthreads();

        const float* q = xyz1 + ((size_t)b * NN_ + n) * 3;
        float qx = q[0], qy = q[1], qz = q[2];
        float sq1 = __fmaf_rn(qz, qz, __fmaf_rn(qy, qy, __fmul_rn(qx, qx)));

        float d0 = FLT_MAX, d1 = FLT_MAX, d2 = FLT_MAX;
        int   i0 = 0, i1 = 0, i2 = 0;

#pragma unroll 4
        for (int s = 0; s < SS; s++) {
            float4 c = sc[s];
            float dot = __fmaf_rn(qz, c.z, __fmaf_rn(qy, c.y, __fmul_rn(qx, c.x)));
            float d = __fsub_rn(__fadd_rn(sq1, c.w), __fadd_rn(dot, dot));
            if (d < d2) {
                if (d < d1) {
                    d2 = d1; i2 = i1;
                    if (d < d0) { d1 = d0; i1 = i0; d0 = d; i0 = s; }
                    else        { d1 = d;  i1 = s; }
                } else { d2 = d; i2 = s; }
            }
        }

        float r0 = __fdiv_rn(1.0f, __fadd_rn(d0, 1e-8f));
        float r1 = __fdiv_rn(1.0f, __fadd_rn(d1, 1e-8f));
        float r2 = __fdiv_rn(1.0f, __fadd_rn(d2, 1e-8f));
        float sum = __fadd_rn(__fadd_rn(r0, r1), r2);

        size_t gi = ((size_t)b * NN_ + n) * 4;
        g_idx4[gi + 0] = i0; g_idx4[gi + 1] = i1;
        g_idx4[gi + 2] = i2; g_idx4[gi + 3] = i2;
        g_w4 [gi + 0] = __fdiv_rn(r0, sum);
        g_w4 [gi + 1] = __fdiv_rn(r1, sum);
        g_w4 [gi + 2] = __fdiv_rn(r2, sum);
        g_w4 [gi + 3] = 0.0f;
    } else {
        // ---------------- Z = Wf2' @ p2 : [b][s][128] ----------------
        float* wch = sbuf;                       // 32*128 = 16KB
        float* ich = sbuf + 4096;                // 32*64  = 8KB
        int b  = blockIdx.y;
        int s0 = blockIdx.x * 64;
        int tid = threadIdx.x;
        int o  = (tid >> 4) * 8;
        int nn = (tid & 15) * 4;

        float acc[8][4];
#pragma unroll
        for (int oi = 0; oi < 8; oi++)
#pragma unroll
            for (int ni = 0; ni < 4; ni++) acc[oi][ni] = 0.0f;

        for (int c0 = 0; c0 < 256; c0 += 32) {
            for (int i = tid; i < 32 * 128 / 4; i += 256)
                ((float4*)wch)[i] = ((const float4*)(g_Wft + (128 + c0) * 128))[i];
            for (int i = tid; i < 32 * 64 / 4; i += 256) {
                int c = i >> 4, sq = (i & 15);
                ((float4*)ich)[i] =
                    *(const float4*)(p2 + ((size_t)b * 256 + c0 + c) * SS + s0 + sq * 4);
            }
            __syncthreads();
#pragma unroll 4
            for (int k = 0; k < 32; k++) {
                float4 w0 = *(const float4*)(wch + k * 128 + o);
                float4 w1 = *(const float4*)(wch + k * 128 + o + 4);
                float4 xv = *(const float4*)(ich + k * 64 + nn);
                float wv[8] = {w0.x, w0.y, w0.z, w0.w, w1.x, w1.y, w1.z, w1.w};
                float xa[4] = {xv.x, xv.y, xv.z, xv.w};
#pragma unroll
                for (int oi = 0; oi < 8; oi++)
#pragma unroll
                    for (int ni = 0; ni < 4; ni++)
                        acc[oi][ni] = fmaf(wv[oi], xa[ni], acc[oi][ni]);
            }
            __syncthreads();
        }
#pragma unroll
        for (int ni = 0; ni < 4; ni++) {
            float* zp = g_Z + ((size_t)b * SS + s0 + nn + ni) * 128 + o;
            *(float4*)(zp)     = make_float4(acc[0][ni], acc[1][ni], acc[2][ni], acc[3][ni]);
            *(float4*)(zp + 4) = make_float4(acc[4][ni], acc[5][ni], acc[6][ni], acc[7][ni]);
        }
    }
}

// ---------------- packed GEMM 64-k chunk (FFMA2, 2-D warp tiling) --------
// Warp covers 32o x 32n; per k per warp: 2 w-LDS (64B each, conflict-free)
// + 1 x-LDS (128B, 4-lane broadcast) = 3 wavefronts.
// Bit-exact: one fp32 FMA per output per k, k ascending.
__device__ __forceinline__ void gemm_chunk(const float* __restrict__ wb,
                                           const float* __restrict__ xb,
                                           int o, int nn,
                                           unsigned long long acc2[4][4])
{
#pragma unroll 4
    for (int k = 0; k < 64; k++) {
        ulonglong2 wA = *(const ulonglong2*)(wb + k * 128 + o);
        ulonglong2 wB = *(const ulonglong2*)(wb + k * 128 + o + 4);
        float4 xv = *(const float4*)(xb + k * NT + nn);
        unsigned long long x0 = pack2(xv.x), x1 = pack2(xv.y);
        unsigned long long x2 = pack2(xv.z), x3 = pack2(xv.w);
        ffma2(acc2[0][0], wA.x, x0); ffma2(acc2[0][1], wA.x, x1);
        ffma2(acc2[0][2], wA.x, x2); ffma2(acc2[0][3], wA.x, x3);
        ffma2(acc2[1][0], wA.y, x0); ffma2(acc2[1][1], wA.y, x1);
        ffma2(acc2[1][2], wA.y, x2); ffma2(acc2[1][3], wA.y, x3);
        ffma2(acc2[2][0], wB.x, x0); ffma2(acc2[2][1], wB.x, x1);
        ffma2(acc2[2][2], wB.x, x2); ffma2(acc2[2][3], wB.x, x3);
        ffma2(acc2[3][0], wB.y, x0); ffma2(acc2[3][1], wB.y, x1);
        ffma2(acc2[3][2], wB.y, x2); ffma2(acc2[3][3], wB.y, x3);
    }
}

__device__ __forceinline__ void zero_acc(unsigned long long acc2[4][4])
{
#pragma unroll
    for (int wp = 0; wp < 4; wp++)
#pragma unroll
        for (int ni = 0; ni < 4; ni++) acc2[wp][ni] = 0ULL;
}

__device__ __forceinline__ void unpack_acc(const unsigned long long acc2[4][4],
                                           float acc[8][4])
{
#pragma unroll
    for (int wp = 0; wp < 4; wp++)
#pragma unroll
        for (int ni = 0; ni < 4; ni++)
            unpack2(acc2[wp][ni], acc[2 * wp][ni], acc[2 * wp + 1][ni]);
}

// ---------------- fused MLP: interpZ-init + fuse(K=128) + residual block --
// smem (floats): wbuf0 8192 | wbuf1 8192 | A 16384 (p1, later h) | B 16384 (x)
__global__ __launch_bounds__(512) void mlp_kernel(
    const float* __restrict__ p1, float* __restrict__ out)
{
    extern __shared__ __align__(16) float smem[];
    float* wbuf0 = smem;
    float* wbuf1 = smem + 8192;
    float* Abuf  = smem + 16384;
    float* Bbuf  = smem + 32768;

    int b   = blockIdx.y;
    int n0  = blockIdx.x * NT;
    int tid = threadIdx.x;
    int wid = tid >> 5, lane = tid & 31;
    // 2-D warp tiling: warp (wid&3, wid>>2) covers 32o x 32n
    int o   = (wid & 3) * 32 + (lane & 3) * 8;
    int nn  = (wid >> 2) * 32 + (lane >> 2) * 4;

    const float4* wfF = (const float4*)g_Wft;    // fuse rows 0..127
    const float4* w1F = (const float4*)g_W1t;
    const float4* w2F = (const float4*)g_W2t;

    float4 pw[4];
#pragma unroll
    for (int i = 0; i < 4; i++) pw[i] = wfF[tid + i * 512];   // fuse chunk 0

    // --- stage p1 tile [128k x 128n] into A ---
#pragma unroll
    for (int i = 0; i < 8; i++) {
        int idx = tid + i * 512;
        int row = idx >> 5, c4 = idx & 31;
        ((float4*)Abuf)[idx] =
            *(const float4*)(p1 + ((size_t)b * 128 + row) * NN_ + n0 + c4 * 4);
    }

    // --- interp-of-Z init: acc[oi][ni] = sum_i w_i * Z[j_i][o+oi] ---
    float acc[8][4];
#pragma unroll
    for (int ni = 0; ni < 4; ni++) {
        size_t gi = ((size_t)b * NN_ + n0 + nn + ni) * 4;
        int4   jj = *(const int4*)(g_idx4 + gi);
        float4 ww = *(const float4*)(g_w4 + gi);
        const float* za = g_Z + ((size_t)b * SS + jj.x) * 128 + o;
        const float* zb = g_Z + ((size_t)b * SS + jj.y) * 128 + o;
        const float* zc = g_Z + ((size_t)b * SS + jj.z) * 128 + o;
        float4 a0 = *(const float4*)(za), a1 = *(const float4*)(za + 4);
        float4 b0 = *(const float4*)(zb), b1 = *(const float4*)(zb + 4);
        float4 c0 = *(const float4*)(zc), c1 = *(const float4*)(zc + 4);
        float av[8] = {a0.x, a0.y, a0.z, a0.w, a1.x, a1.y, a1.z, a1.w};
        float bv[8] = {b0.x, b0.y, b0.z, b0.w, b1.x, b1.y, b1.z, b1.w};
        float cv[8] = {c0.x, c0.y, c0.z, c0.w, c1.x, c1.y, c1.z, c1.w};
#pragma unroll
        for (int oi = 0; oi < 8; oi++)
            acc[oi][ni] = fmaf(ww.z, cv[oi], fmaf(ww.y, bv[oi], ww.x * av[oi]));
    }
    unsigned long long acc2[4][4];
#pragma unroll
    for (int wp = 0; wp < 4; wp++)
#pragma unroll
        for (int ni = 0; ni < 4; ni++)
            acc2[wp][ni] = pack2p(acc[2 * wp][ni], acc[2 * wp + 1][ni]);

#pragma unroll
    for (int i = 0; i < 4; i++) ((float4*)wbuf0)[tid + i * 512] = pw[i];
    __syncthreads();                                     // A + wbuf0 ready

    // --- fuse chunk 0 ---
#pragma unroll
    for (int i = 0; i < 4; i++) pw[i] = wfF[2048 + tid + i * 512];  // fuse chunk 1
    gemm_chunk(wbuf0, Abuf, o, nn, acc2);
#pragma unroll
    for (int i = 0; i < 4; i++) ((float4*)wbuf1)[tid + i * 512] = pw[i];
    __syncthreads();

    // --- fuse chunk 1 ---
#pragma unroll
    for (int i = 0; i < 4; i++) pw[i] = w1F[tid + i * 512];         // c1 chunk 0
    gemm_chunk(wbuf1, Abuf + 64 * NT, o, nn, acc2);
#pragma unroll
    for (int i = 0; i < 4; i++) ((float4*)wbuf0)[tid + i * 512] = pw[i];
    __syncthreads();

    // --- fuse epilogue: x = relu(bn_f(acc)) -> B ---
    {
        unpack_acc(acc2, acc);
        float4 s0 = *(const float4*)(g_scale_f + o);
        float4 s1 = *(const float4*)(g_scale_f + o + 4);
        float4 t0 = *(const float4*)(g_bias_f + o);
        float4 t1 = *(const float4*)(g_bias_f + o + 4);
        float sv[8] = {s0.x, s0.y, s0.z, s0.w, s1.x, s1.y, s1.z, s1.w};
        float tv[8] = {t0.x, t0.y, t0.z, t0.w, t1.x, t1.y, t1.z, t1.w};
#pragma unroll
        for (int oi = 0; oi < 8; oi++) {
            float4 xr;
            xr.x = fmaxf(fmaf(sv[oi], acc[oi][0], tv[oi]), 0.0f);
            xr.y = fmaxf(fmaf(sv[oi], acc[oi][1], tv[oi]), 0.0f);
            xr.z = fmaxf(fmaf(sv[oi], acc[oi][2], tv[oi]), 0.0f);
            xr.w = fmaxf(fmaf(sv[oi], acc[oi][3], tv[oi]), 0.0f);
            *(float4*)(Bbuf + (o + oi) * NT + nn) = xr;
        }
    }
#pragma unroll
    for (int i = 0; i < 4; i++) pw[i] = w1F[2048 + tid + i * 512];  // c1 chunk 1
    __syncthreads();                                     // B visible

    // --- c1 chunk 0 ---
    zero_acc(acc2);
    gemm_chunk(wbuf0, Bbuf, o, nn, acc2);
#pragma unroll
    for (int i = 0; i < 4; i++) ((float4*)wbuf1)[tid + i * 512] = pw[i];
    __syncthreads();

    // --- c1 chunk 1 ---
#pragma unroll
    for (int i = 0; i < 4; i++) pw[i] = w2F[tid + i * 512];         // c2 chunk 0
    gemm_chunk(wbuf1, Bbuf + 64 * NT, o, nn, acc2);
#pragma unroll
    for (int i = 0; i < 4; i++) ((float4*)wbuf0)[tid + i * 512] = pw[i];
    __syncthreads();

    // --- c1 epilogue: h = relu(bn1(acc)) -> A (p1 dead) ---
    {
        unpack_acc(acc2, acc);
        float4 s0 = *(const float4*)(g_scale_1 + o);
        float4 s1 = *(const float4*)(g_scale_1 + o + 4);
        float4 t0 = *(const float4*)(g_bias_1 + o);
        float4 t1 = *(const float4*)(g_bias_1 + o + 4);
        float sv[8] = {s0.x, s0.y, s0.z, s0.w, s1.x, s1.y, s1.z, s1.w};
        float tv[8] = {t0.x, t0.y, t0.z, t0.w, t1.x, t1.y, t1.z, t1.w};
#pragma unroll
        for (int oi = 0; oi < 8; oi++) {
            float4 hv;
            hv.x = fmaxf(fmaf(sv[oi], acc[oi][0], tv[oi]), 0.0f);
            hv.y = fmaxf(fmaf(sv[oi], acc[oi][1], tv[oi]), 0.0f);
            hv.z = fmaxf(fmaf(sv[oi], acc[oi][2], tv[oi]), 0.0f);
            hv.w = fmaxf(fmaf(sv[oi], acc[oi][3], tv[oi]), 0.0f);
            *(float4*)(Abuf + (o + oi) * NT + nn) = hv;
        }
    }
#pragma unroll
    for (int i = 0; i < 4; i++) pw[i] = w2F[2048 + tid + i * 512];  // c2 chunk 1
    __syncthreads();                                     // A(h) visible

    // --- c2 chunk 0 ---
    zero_acc(acc2);
    gemm_chunk(wbuf0, Abuf, o, nn, acc2);
#pragma unroll
    for (int i = 0; i < 4; i++) ((float4*)wbuf1)[tid + i * 512] = pw[i];
    __syncthreads();

    // --- c2 chunk 1 ---
    gemm_chunk(wbuf1, Abuf + 64 * NT, o, nn, acc2);

    // --- c2 epilogue: out = relu(bn2(acc) + x) ---
    {
        unpack_acc(acc2, acc);
        float4 s0 = *(const float4*)(g_scale_2 + o);
        float4 s1 = *(const float4*)(g_scale_2 + o + 4);
        float4 t0 = *(const float4*)(g_bias_2 + o);
        float4 t1 = *(const float4*)(g_bias_2 + o + 4);
        float sv[8] = {s0.x, s0.y, s0.z, s0.w, s1.x, s1.y, s1.z, s1.w};
        float tv[8] = {t0.x, t0.y, t0.z, t0.w, t1.x, t1.y, t1.z, t1.w};
#pragma unroll
        for (int oi = 0; oi < 8; oi++) {
            float4 xr = *(const float4*)(Bbuf + (o + oi) * NT + nn);
            float* op = out + ((size_t)b * 128 + o + oi) * NN_ + n0 + nn;
            *(float4*)op = make_float4(
                fmaxf(fmaf(sv[oi], acc[oi][0], tv[oi]) + xr.x, 0.0f),
                fmaxf(fmaf(sv[oi], acc[oi][1], tv[oi]) + xr.y, 0.0f),
                fmaxf(fmaf(sv[oi], acc[oi][2], tv[oi]) + xr.z, 0.0f),
                fmaxf(fmaf(sv[oi], acc[oi][3], tv[oi]) + xr.w, 0.0f));
        }
    }
}

// ---------------- launch ----------------
extern "C" void kernel_launch(void* const* d_in, const int* in_sizes, int n_in,
                              void* d_out, int out_size)
{
    const float* xyz1      = (const float*)d_in[0];
    const float* xyz2      = (const float*)d_in[1];
    const float* points1   = (const float*)d_in[2];
    const float* points2   = (const float*)d_in[3];
    const float* fuse_w    = (const float*)d_in[4];
    const float* fuse_b    = (const float*)d_in[5];
    const float* fuse_g    = (const float*)d_in[6];
    const float* fuse_beta = (const float*)d_in[7];
    const float* fuse_m    = (const float*)d_in[8];
    const float* fuse_v    = (const float*)d_in[9];
    const float* c1_w      = (const float*)d_in[10];
    const float* c1_b      = (const float*)d_in[11];
    const float* bn1_g     = (const float*)d_in[12];
    const float* bn1_b     = (const float*)d_in[13];
    const float* bn1_m     = (const float*)d_in[14];
    const float* bn1_v     = (const float*)d_in[15];
    const float* c2_w      = (const float*)d_in[16];
    const float* c2_b      = (const float*)d_in[17];
    const float* bn2_g     = (const float*)d_in[18];
    const float* bn2_b     = (const float*)d_in[19];
    const float* bn2_m     = (const float*)d_in[20];
    const float* bn2_v     = (const float*)d_in[21];
    float* out = (float*)d_out;

    cudaFuncSetAttribute(mlp_kernel,
                         cudaFuncAttributeMaxDynamicSharedMemorySize, 196608);

    prep_kernel<<<128, 256>>>(fuse_w, fuse_b, fuse_g, fuse_beta, fuse_m, fuse_v,
                              c1_w, c1_b, bn1_g, bn1_b, bn1_m, bn1_v,
                              c2_w, c2_b, bn2_g, bn2_b, bn2_m, bn2_v);
    knn_zgemm_kernel<<<dim3(16, BB, 2), 256>>>(xyz1, xyz2, points2);
    mlp_kernel<<<dim3(NN_ / NT, BB), 512, 196608>>>(points1, out);
}